// round 3
// baseline (speedup 1.0000x reference)
#include <cuda_runtime.h>
#include <cstdint>

#define N_TOK 4096
#define EMBED 1024
#define NHEAD 16
#define HDIM 64
#define FFN 4096
#define QKV3 3072

// ---------------- scratch (device globals; no allocation) ----------------
__device__ float g_qkv[N_TOK * QKV3];       // [n][3][16][64]
__device__ float g_att[N_TOK * EMBED];      // attention output (n, h*64+d)
__device__ float g_o  [N_TOK * EMBED];      // after Wo
__device__ float g_h  [N_TOK * EMBED];      // LN1 output
__device__ float g_f1 [N_TOK * FFN];        // gelu(h@W1+b1)
__device__ float g_f2 [N_TOK * EMBED];      // f1@W2+b2
__device__ int   g_seg[N_TOK];
__device__ int   g_segstart[N_TOK];
__device__ int   g_segend[N_TOK];

// ---------------- segment ids ----------------
__global__ void seg_kernel(const int* __restrict__ cu) {
    int n = blockIdx.x * blockDim.x + threadIdx.x;
    if (n >= N_TOK) return;
    int s = 0;
#pragma unroll
    for (int i = 1; i <= 8; i++) s += (cu[i] <= n) ? 1 : 0;
    g_seg[n] = s;
    g_segstart[n] = cu[s];
    g_segend[n] = cu[s + 1];
}

// ---------------- RoPE on q and k ----------------
__global__ void rope_kernel(const float* __restrict__ coords,
                            const float* __restrict__ invf) {
    int idx = blockIdx.x * blockDim.x + threadIdx.x;
    if (idx >= N_TOK * NHEAD * 32) return;
    int j = idx & 31;
    int h = (idx >> 5) & 15;
    int n = idx >> 9;
    float ang = coords[n * 4 + (j >> 3)] * invf[j];
    float s, c;
    sincosf(ang, &s, &c);
    size_t base = (size_t)n * QKV3 + h * HDIM;
#pragma unroll
    for (int part = 0; part < 2; part++) {
        float* p = g_qkv + base + part * EMBED;
        float x1 = p[j], x2 = p[j + 32];
        p[j]      = x1 * c - x2 * s;
        p[j + 32] = x2 * c + x1 * s;
    }
}

// ---------------- SGEMM: C[M,N] = A[M,K] @ B[K,N] + bias, optional gelu ----
// 128x128 tile, BK=16, 256 threads, 8x8 microtile.
__device__ __forceinline__ float gelu_f(float x) {
    float x3 = x * x * x;
    return 0.5f * x * (1.0f + tanhf(0.7978845608028654f * (x + 0.044715f * x3)));
}

template <int ACT>
__global__ __launch_bounds__(256) void sgemm_kernel(
    const float* __restrict__ A, const float* __restrict__ B,
    const float* __restrict__ bias, float* __restrict__ C,
    int M, int N, int K) {
    __shared__ float As[16][128];
    __shared__ float Bs[16][128];
    int tid = threadIdx.x;
    int bx = blockIdx.x;   // N tile
    int by = blockIdx.y;   // M tile

    int arow = tid >> 2;           // 0..63
    int acol = (tid & 3) * 4;      // 0,4,8,12
    int brow = tid >> 5;           // 0..7
    int bcol = (tid & 31) * 4;

    int ty = tid >> 4, tx = tid & 15;

    float acc[8][8];
#pragma unroll
    for (int i = 0; i < 8; i++)
#pragma unroll
        for (int j = 0; j < 8; j++) acc[i][j] = 0.f;

    const float* Ap = A + (size_t)(by * 128) * K;
    const float* Bp = B + bx * 128;

    for (int k0 = 0; k0 < K; k0 += 16) {
#pragma unroll
        for (int s = 0; s < 2; s++) {
            int r = arow + s * 64;
            float4 v = *(const float4*)(Ap + (size_t)r * K + k0 + acol);
            As[acol + 0][r] = v.x;
            As[acol + 1][r] = v.y;
            As[acol + 2][r] = v.z;
            As[acol + 3][r] = v.w;
        }
#pragma unroll
        for (int s = 0; s < 2; s++) {
            int r = brow + s * 8;
            *(float4*)&Bs[r][bcol] = *(const float4*)(Bp + (size_t)(k0 + r) * N + bcol);
        }
        __syncthreads();
#pragma unroll
        for (int kk = 0; kk < 16; kk++) {
            float a[8], b[8];
            float4 a0 = *(const float4*)&As[kk][ty * 8];
            float4 a1 = *(const float4*)&As[kk][ty * 8 + 4];
            float4 b0 = *(const float4*)&Bs[kk][tx * 8];
            float4 b1 = *(const float4*)&Bs[kk][tx * 8 + 4];
            a[0]=a0.x;a[1]=a0.y;a[2]=a0.z;a[3]=a0.w;a[4]=a1.x;a[5]=a1.y;a[6]=a1.z;a[7]=a1.w;
            b[0]=b0.x;b[1]=b0.y;b[2]=b0.z;b[3]=b0.w;b[4]=b1.x;b[5]=b1.y;b[6]=b1.z;b[7]=b1.w;
#pragma unroll
            for (int i = 0; i < 8; i++)
#pragma unroll
                for (int j = 0; j < 8; j++) acc[i][j] = fmaf(a[i], b[j], acc[i][j]);
        }
        __syncthreads();
    }

    int cbase = bx * 128 + tx * 8;
    float4 bv0 = *(const float4*)(bias + cbase);
    float4 bv1 = *(const float4*)(bias + cbase + 4);
    float bb[8] = {bv0.x, bv0.y, bv0.z, bv0.w, bv1.x, bv1.y, bv1.z, bv1.w};
#pragma unroll
    for (int i = 0; i < 8; i++) {
        int r = by * 128 + ty * 8 + i;
        float* cp = C + (size_t)r * N + cbase;
        float v[8];
#pragma unroll
        for (int j = 0; j < 8; j++) {
            float x = acc[i][j] + bb[j];
            v[j] = (ACT == 1) ? gelu_f(x) : x;
        }
        *(float4*)cp       = make_float4(v[0], v[1], v[2], v[3]);
        *(float4*)(cp + 4) = make_float4(v[4], v[5], v[6], v[7]);
    }
}

// ---------------- attention: block = (32-query tile, head) ----------------
__global__ __launch_bounds__(256) void attn_kernel() {
    __shared__ float Ks[32][64];
    __shared__ float Vs[32][64];
    __shared__ int   Sg[32];

    int h = blockIdx.y;
    int n0 = blockIdx.x * 32;
    int tid = threadIdx.x;
    int ql = tid >> 3;    // 0..31 query within tile (also key row loaded)
    int sub = tid & 7;    // 0..7 dim group
    int n = n0 + ql;
    int my_seg = g_seg[n];

    const float scale = 0.125f;  // 1/sqrt(64)
    float q[8];
    const float* qp = g_qkv + (size_t)n * QKV3 + h * HDIM + sub * 8;
#pragma unroll
    for (int i = 0; i < 8; i++) q[i] = qp[i] * scale;

    float m = -1e30f, l = 0.f;
    float acc[8];
#pragma unroll
    for (int i = 0; i < 8; i++) acc[i] = 0.f;

    int k_lo = g_segstart[n0];
    int k_hi = g_segend[n0 + 31];

    for (int kt = k_lo; kt < k_hi; kt += 32) {
        int key = kt + ql;
        if (key < k_hi) {
            const float* kp = g_qkv + (size_t)key * QKV3 + EMBED + h * HDIM + sub * 8;
            *(float4*)&Ks[ql][sub * 8]     = *(const float4*)kp;
            *(float4*)&Ks[ql][sub * 8 + 4] = *(const float4*)(kp + 4);
            const float* vp = kp + EMBED;
            *(float4*)&Vs[ql][sub * 8]     = *(const float4*)vp;
            *(float4*)&Vs[ql][sub * 8 + 4] = *(const float4*)(vp + 4);
            if (sub == 0) Sg[ql] = g_seg[key];
        } else {
            *(float4*)&Ks[ql][sub * 8]     = make_float4(0, 0, 0, 0);
            *(float4*)&Ks[ql][sub * 8 + 4] = make_float4(0, 0, 0, 0);
            *(float4*)&Vs[ql][sub * 8]     = make_float4(0, 0, 0, 0);
            *(float4*)&Vs[ql][sub * 8 + 4] = make_float4(0, 0, 0, 0);
            if (sub == 0) Sg[ql] = -1;
        }
        __syncthreads();

        int kmax = min(32, k_hi - kt);
        for (int kk = 0; kk < kmax; kk++) {
            float4 ka = *(const float4*)&Ks[kk][sub * 8];
            float4 kb = *(const float4*)&Ks[kk][sub * 8 + 4];
            float p = q[0] * ka.x + q[1] * ka.y + q[2] * ka.z + q[3] * ka.w +
                      q[4] * kb.x + q[5] * kb.y + q[6] * kb.z + q[7] * kb.w;
            p += __shfl_xor_sync(0xffffffffu, p, 1);
            p += __shfl_xor_sync(0xffffffffu, p, 2);
            p += __shfl_xor_sync(0xffffffffu, p, 4);
            if (Sg[kk] == my_seg) {
                float nm = fmaxf(m, p);
                float corr = __expf(m - nm);
                float e = __expf(p - nm);
                l = l * corr + e;
                float4 va = *(const float4*)&Vs[kk][sub * 8];
                float4 vb = *(const float4*)&Vs[kk][sub * 8 + 4];
                acc[0] = acc[0] * corr + e * va.x;
                acc[1] = acc[1] * corr + e * va.y;
                acc[2] = acc[2] * corr + e * va.z;
                acc[3] = acc[3] * corr + e * va.w;
                acc[4] = acc[4] * corr + e * vb.x;
                acc[5] = acc[5] * corr + e * vb.y;
                acc[6] = acc[6] * corr + e * vb.z;
                acc[7] = acc[7] * corr + e * vb.w;
                m = nm;
            }
        }
        __syncthreads();
    }

    float inv = 1.f / l;
    float* op = g_att + (size_t)n * EMBED + h * HDIM + sub * 8;
#pragma unroll
    for (int i = 0; i < 8; i++) op[i] = acc[i] * inv;
}

// ---------------- residual + layernorm ----------------
__device__ __forceinline__ float block_reduce_sum(float v) {
    __shared__ float sh[8];
    int lane = threadIdx.x & 31, w = threadIdx.x >> 5;
#pragma unroll
    for (int o = 16; o; o >>= 1) v += __shfl_xor_sync(0xffffffffu, v, o);
    if (!lane) sh[w] = v;
    __syncthreads();
    if (w == 0) {
        v = (lane < 8) ? sh[lane] : 0.f;
#pragma unroll
        for (int o = 4; o; o >>= 1) v += __shfl_xor_sync(0xffffffffu, v, o);
        if (!lane) sh[0] = v;
    }
    __syncthreads();
    float r = sh[0];
    __syncthreads();
    return r;
}

__global__ __launch_bounds__(256) void ln_kernel(
    const float* __restrict__ A, const float* __restrict__ R,
    const float* __restrict__ g, const float* __restrict__ b,
    float* __restrict__ out) {
    int row = blockIdx.x;
    int tid = threadIdx.x;
    const float* a = A + (size_t)row * EMBED;
    const float* r = R + (size_t)row * EMBED;
    float x[4];
    float s = 0.f;
#pragma unroll
    for (int i = 0; i < 4; i++) {
        x[i] = a[tid + i * 256] + r[tid + i * 256];
        s += x[i];
    }
    float mu = block_reduce_sum(s) * (1.0f / EMBED);
    float sq = 0.f;
#pragma unroll
    for (int i = 0; i < 4; i++) {
        float d = x[i] - mu;
        sq += d * d;
    }
    float var = block_reduce_sum(sq) * (1.0f / EMBED);
    float inv = rsqrtf(var + 1e-5f);
#pragma unroll
    for (int i = 0; i < 4; i++) {
        int c = tid + i * 256;
        out[(size_t)row * EMBED + c] = (x[i] - mu) * inv * g[c] + b[c];
    }
}

// ---------------- launch ----------------
extern "C" void kernel_launch(void* const* d_in, const int* in_sizes, int n_in,
                              void* d_out, int out_size) {
    const float* coords   = (const float*)d_in[0];
    const float* feats    = (const float*)d_in[1];
    const int*   cu       = (const int*)  d_in[2];
    const float* Wqkv     = (const float*)d_in[3];
    const float* bqkv     = (const float*)d_in[4];
    const float* Wo       = (const float*)d_in[5];
    const float* bo       = (const float*)d_in[6];
    const float* inv_freq = (const float*)d_in[7];
    const float* ln1_g    = (const float*)d_in[8];
    const float* ln1_b    = (const float*)d_in[9];
    const float* W1       = (const float*)d_in[10];
    const float* b1       = (const float*)d_in[11];
    const float* W2       = (const float*)d_in[12];
    const float* b2       = (const float*)d_in[13];
    const float* ln2_g    = (const float*)d_in[14];
    const float* ln2_b    = (const float*)d_in[15];
    float* out = (float*)d_out;

    float *p_qkv, *p_att, *p_o, *p_h, *p_f1, *p_f2;
    cudaGetSymbolAddress((void**)&p_qkv, g_qkv);
    cudaGetSymbolAddress((void**)&p_att, g_att);
    cudaGetSymbolAddress((void**)&p_o,   g_o);
    cudaGetSymbolAddress((void**)&p_h,   g_h);
    cudaGetSymbolAddress((void**)&p_f1,  g_f1);
    cudaGetSymbolAddress((void**)&p_f2,  g_f2);

    // 1. segments
    seg_kernel<<<(N_TOK + 255) / 256, 256>>>(cu);

    // 2. qkv = feats @ Wqkv + bqkv   [4096 x 3072]
    sgemm_kernel<0><<<dim3(QKV3 / 128, N_TOK / 128), 256>>>(feats, Wqkv, bqkv, p_qkv,
                                                            N_TOK, QKV3, EMBED);
    // 3. rope on q,k
    rope_kernel<<<(N_TOK * NHEAD * 32 + 255) / 256, 256>>>(coords, inv_freq);

    // 4. attention -> g_att
    attn_kernel<<<dim3(N_TOK / 32, NHEAD), 256>>>();

    // 5. o = att @ Wo + bo
    sgemm_kernel<0><<<dim3(EMBED / 128, N_TOK / 128), 256>>>(p_att, Wo, bo, p_o,
                                                             N_TOK, EMBED, EMBED);
    // 6. h = LN1(feats + o)
    ln_kernel<<<N_TOK, 256>>>(feats, p_o, ln1_g, ln1_b, p_h);

    // 7. f1 = gelu(h @ W1 + b1)
    sgemm_kernel<1><<<dim3(FFN / 128, N_TOK / 128), 256>>>(p_h, W1, b1, p_f1,
                                                           N_TOK, FFN, EMBED);
    // 8. f2 = f1 @ W2 + b2
    sgemm_kernel<0><<<dim3(EMBED / 128, N_TOK / 128), 256>>>(p_f1, W2, b2, p_f2,
                                                             N_TOK, EMBED, FFN);
    // 9. out = LN2(h + f2)
    ln_kernel<<<N_TOK, 256>>>(p_h, p_f2, ln2_g, ln2_b, out);
}

// round 4
// speedup vs baseline: 1.5052x; 1.5052x over previous
#include <cuda_runtime.h>
#include <cstdint>

#define N_TOK 4096
#define EMBED 1024
#define NHEAD 16
#define HDIM 64
#define FFN 4096
#define QKV3 3072

// ---------------- scratch (device globals; no allocation) ----------------
__device__ float g_qkv[N_TOK * QKV3];       // [n][3][16][64]
__device__ float g_att[N_TOK * EMBED];      // attention output (n, h*64+d)
__device__ float g_o  [N_TOK * EMBED];      // after Wo
__device__ float g_h  [N_TOK * EMBED];      // LN1 output
__device__ float g_f1 [N_TOK * FFN];        // gelu(h@W1+b1)
__device__ float g_f2 [N_TOK * EMBED];      // f1@W2+b2
__device__ int   g_seg[N_TOK];
__device__ int   g_segstart[N_TOK];
__device__ int   g_segend[N_TOK];

// ---------------- segment ids ----------------
__global__ void seg_kernel(const int* __restrict__ cu) {
    int n = blockIdx.x * blockDim.x + threadIdx.x;
    if (n >= N_TOK) return;
    int s = 0;
#pragma unroll
    for (int i = 1; i <= 8; i++) s += (cu[i] <= n) ? 1 : 0;
    g_seg[n] = s;
    g_segstart[n] = cu[s];
    g_segend[n] = cu[s + 1];
}

// ---------------- RoPE on q and k ----------------
__global__ void rope_kernel(const float* __restrict__ coords,
                            const float* __restrict__ invf) {
    int idx = blockIdx.x * blockDim.x + threadIdx.x;
    if (idx >= N_TOK * NHEAD * 32) return;
    int j = idx & 31;
    int h = (idx >> 5) & 15;
    int n = idx >> 9;
    float ang = coords[n * 4 + (j >> 3)] * invf[j];
    float s, c;
    sincosf(ang, &s, &c);
    size_t base = (size_t)n * QKV3 + h * HDIM;
#pragma unroll
    for (int part = 0; part < 2; part++) {
        float* p = g_qkv + base + part * EMBED;
        float x1 = p[j], x2 = p[j + 32];
        p[j]      = x1 * c - x2 * s;
        p[j + 32] = x2 * c + x1 * s;
    }
}

// ---------------- TF32 tensor-core GEMM ----------------
// C[M,N] = A[M,K] @ B[K,N] + bias, optional gelu.
// 128x128 block tile, BK=16, 256 threads (8 warps), warp tile 64x32,
// mma.sync.m16n8k8.tf32, double-buffered smem + register staging.

__device__ __forceinline__ float gelu_f(float x) {
    float x3 = x * x * x;
    return 0.5f * x * (1.0f + tanhf(0.7978845608028654f * (x + 0.044715f * x3)));
}

__device__ __forceinline__ uint32_t f2tf(float f) {
    uint32_t u;
    asm("cvt.rna.tf32.f32 %0, %1;" : "=r"(u) : "f"(f));
    return u;
}

__device__ __forceinline__ void mma_tf32(float c[4], const uint32_t a[4], const uint32_t b[2]) {
    asm volatile(
        "mma.sync.aligned.m16n8k8.row.col.f32.tf32.tf32.f32 "
        "{%0,%1,%2,%3}, {%4,%5,%6,%7}, {%8,%9}, {%0,%1,%2,%3};\n"
        : "+f"(c[0]), "+f"(c[1]), "+f"(c[2]), "+f"(c[3])
        : "r"(a[0]), "r"(a[1]), "r"(a[2]), "r"(a[3]), "r"(b[0]), "r"(b[1]));
}

template <int ACT>
__global__ __launch_bounds__(256, 2) void tf32gemm_kernel(
    const float* __restrict__ A, const float* __restrict__ B,
    const float* __restrict__ bias, float* __restrict__ C,
    int M, int N, int K) {
    __shared__ uint32_t As[2][128][20];   // [m][k] padded: conflict-free frag loads
    __shared__ uint32_t Bs[2][16][136];   // [k][n] padded: conflict-free frag loads

    int tid = threadIdx.x;
    int bm = blockIdx.y * 128;
    int bn = blockIdx.x * 128;

    int warp = tid >> 5;
    int lane = tid & 31;
    int g = lane >> 2;     // 0..7
    int t = lane & 3;      // 0..3
    int warp_m = (warp & 1) * 64;
    int warp_n = (warp >> 1) * 32;

    // staging: each thread moves 8 floats of A and 8 floats of B per BK tile
    int ldA_m = tid >> 1;          // 0..127
    int ldA_k = (tid & 1) * 8;     // 0 or 8
    int ldB_k = tid >> 4;          // 0..15
    int ldB_n = (tid & 15) * 8;    // 0..120

    const float* Ag = A + (size_t)(bm + ldA_m) * K + ldA_k;
    const float* Bg = B + (size_t)ldB_k * N + bn + ldB_n;

    float acc[4][4][4];
#pragma unroll
    for (int i = 0; i < 4; i++)
#pragma unroll
        for (int j = 0; j < 4; j++)
#pragma unroll
            for (int r = 0; r < 4; r++) acc[i][j][r] = 0.f;

    // prologue: load tile 0 into regs, convert, store to buf 0
    float4 ra0 = *(const float4*)Ag;
    float4 ra1 = *(const float4*)(Ag + 4);
    float4 rb0 = *(const float4*)Bg;
    float4 rb1 = *(const float4*)(Bg + 4);
    As[0][ldA_m][ldA_k + 0] = f2tf(ra0.x);
    As[0][ldA_m][ldA_k + 1] = f2tf(ra0.y);
    As[0][ldA_m][ldA_k + 2] = f2tf(ra0.z);
    As[0][ldA_m][ldA_k + 3] = f2tf(ra0.w);
    As[0][ldA_m][ldA_k + 4] = f2tf(ra1.x);
    As[0][ldA_m][ldA_k + 5] = f2tf(ra1.y);
    As[0][ldA_m][ldA_k + 6] = f2tf(ra1.z);
    As[0][ldA_m][ldA_k + 7] = f2tf(ra1.w);
    Bs[0][ldB_k][ldB_n + 0] = f2tf(rb0.x);
    Bs[0][ldB_k][ldB_n + 1] = f2tf(rb0.y);
    Bs[0][ldB_k][ldB_n + 2] = f2tf(rb0.z);
    Bs[0][ldB_k][ldB_n + 3] = f2tf(rb0.w);
    Bs[0][ldB_k][ldB_n + 4] = f2tf(rb1.x);
    Bs[0][ldB_k][ldB_n + 5] = f2tf(rb1.y);
    Bs[0][ldB_k][ldB_n + 6] = f2tf(rb1.z);
    Bs[0][ldB_k][ldB_n + 7] = f2tf(rb1.w);
    __syncthreads();

    int nk = K >> 4;
    for (int kt = 0; kt < nk; kt++) {
        int cur = kt & 1;
        // prefetch next BK tile into registers (overlaps with compute below)
        if (kt + 1 < nk) {
            const float* Ap = Ag + (kt + 1) * 16;
            const float* Bp = Bg + (size_t)(kt + 1) * 16 * N;
            ra0 = *(const float4*)Ap;
            ra1 = *(const float4*)(Ap + 4);
            rb0 = *(const float4*)Bp;
            rb1 = *(const float4*)(Bp + 4);
        }

#pragma unroll
        for (int ks = 0; ks < 16; ks += 8) {
            uint32_t af[4][4], bf[4][2];
#pragma unroll
            for (int i = 0; i < 4; i++) {
                int m0 = warp_m + i * 16 + g;
                af[i][0] = As[cur][m0][ks + t];
                af[i][1] = As[cur][m0 + 8][ks + t];
                af[i][2] = As[cur][m0][ks + t + 4];
                af[i][3] = As[cur][m0 + 8][ks + t + 4];
            }
#pragma unroll
            for (int j = 0; j < 4; j++) {
                int n0 = warp_n + j * 8 + g;
                bf[j][0] = Bs[cur][ks + t][n0];
                bf[j][1] = Bs[cur][ks + t + 4][n0];
            }
#pragma unroll
            for (int i = 0; i < 4; i++)
#pragma unroll
                for (int j = 0; j < 4; j++)
                    mma_tf32(acc[i][j], af[i], bf[j]);
        }

        if (kt + 1 < nk) {
            int nxt = cur ^ 1;
            As[nxt][ldA_m][ldA_k + 0] = f2tf(ra0.x);
            As[nxt][ldA_m][ldA_k + 1] = f2tf(ra0.y);
            As[nxt][ldA_m][ldA_k + 2] = f2tf(ra0.z);
            As[nxt][ldA_m][ldA_k + 3] = f2tf(ra0.w);
            As[nxt][ldA_m][ldA_k + 4] = f2tf(ra1.x);
            As[nxt][ldA_m][ldA_k + 5] = f2tf(ra1.y);
            As[nxt][ldA_m][ldA_k + 6] = f2tf(ra1.z);
            As[nxt][ldA_m][ldA_k + 7] = f2tf(ra1.w);
            Bs[nxt][ldB_k][ldB_n + 0] = f2tf(rb0.x);
            Bs[nxt][ldB_k][ldB_n + 1] = f2tf(rb0.y);
            Bs[nxt][ldB_k][ldB_n + 2] = f2tf(rb0.z);
            Bs[nxt][ldB_k][ldB_n + 3] = f2tf(rb0.w);
            Bs[nxt][ldB_k][ldB_n + 4] = f2tf(rb1.x);
            Bs[nxt][ldB_k][ldB_n + 5] = f2tf(rb1.y);
            Bs[nxt][ldB_k][ldB_n + 6] = f2tf(rb1.z);
            Bs[nxt][ldB_k][ldB_n + 7] = f2tf(rb1.w);
        }
        __syncthreads();
    }

    // epilogue: bias (+gelu) and store
#pragma unroll
    for (int j = 0; j < 4; j++) {
        int col = bn + warp_n + j * 8 + 2 * t;
        float2 bb = *(const float2*)(bias + col);
#pragma unroll
        for (int i = 0; i < 4; i++) {
            int r = bm + warp_m + i * 16 + g;
            float x0 = acc[i][j][0] + bb.x;
            float x1 = acc[i][j][1] + bb.y;
            float x2 = acc[i][j][2] + bb.x;
            float x3 = acc[i][j][3] + bb.y;
            if (ACT == 1) {
                x0 = gelu_f(x0); x1 = gelu_f(x1);
                x2 = gelu_f(x2); x3 = gelu_f(x3);
            }
            *(float2*)(C + (size_t)r * N + col)       = make_float2(x0, x1);
            *(float2*)(C + (size_t)(r + 8) * N + col) = make_float2(x2, x3);
        }
    }
}

// ---------------- attention: block = (32-query tile, head) ----------------
__global__ __launch_bounds__(256) void attn_kernel() {
    __shared__ float Ks[32][64];
    __shared__ float Vs[32][64];
    __shared__ int   Sg[32];

    int h = blockIdx.y;
    int n0 = blockIdx.x * 32;
    int tid = threadIdx.x;
    int ql = tid >> 3;    // 0..31 query within tile (also key row loaded)
    int sub = tid & 7;    // 0..7 dim group
    int n = n0 + ql;
    int my_seg = g_seg[n];

    const float scale = 0.125f;  // 1/sqrt(64)
    float q[8];
    const float* qp = g_qkv + (size_t)n * QKV3 + h * HDIM + sub * 8;
#pragma unroll
    for (int i = 0; i < 8; i++) q[i] = qp[i] * scale;

    float m = -1e30f, l = 0.f;
    float acc[8];
#pragma unroll
    for (int i = 0; i < 8; i++) acc[i] = 0.f;

    int k_lo = g_segstart[n0];
    int k_hi = g_segend[n0 + 31];

    for (int kt = k_lo; kt < k_hi; kt += 32) {
        int key = kt + ql;
        if (key < k_hi) {
            const float* kp = g_qkv + (size_t)key * QKV3 + EMBED + h * HDIM + sub * 8;
            *(float4*)&Ks[ql][sub * 8]     = *(const float4*)kp;
            *(float4*)&Ks[ql][sub * 8 + 4] = *(const float4*)(kp + 4);
            const float* vp = kp + EMBED;
            *(float4*)&Vs[ql][sub * 8]     = *(const float4*)vp;
            *(float4*)&Vs[ql][sub * 8 + 4] = *(const float4*)(vp + 4);
            if (sub == 0) Sg[ql] = g_seg[key];
        } else {
            *(float4*)&Ks[ql][sub * 8]     = make_float4(0, 0, 0, 0);
            *(float4*)&Ks[ql][sub * 8 + 4] = make_float4(0, 0, 0, 0);
            *(float4*)&Vs[ql][sub * 8]     = make_float4(0, 0, 0, 0);
            *(float4*)&Vs[ql][sub * 8 + 4] = make_float4(0, 0, 0, 0);
            if (sub == 0) Sg[ql] = -1;
        }
        __syncthreads();

        int kmax = min(32, k_hi - kt);
        for (int kk = 0; kk < kmax; kk++) {
            float4 ka = *(const float4*)&Ks[kk][sub * 8];
            float4 kb = *(const float4*)&Ks[kk][sub * 8 + 4];
            float p = q[0] * ka.x + q[1] * ka.y + q[2] * ka.z + q[3] * ka.w +
                      q[4] * kb.x + q[5] * kb.y + q[6] * kb.z + q[7] * kb.w;
            p += __shfl_xor_sync(0xffffffffu, p, 1);
            p += __shfl_xor_sync(0xffffffffu, p, 2);
            p += __shfl_xor_sync(0xffffffffu, p, 4);
            if (Sg[kk] == my_seg) {
                float nm = fmaxf(m, p);
                float corr = __expf(m - nm);
                float e = __expf(p - nm);
                l = l * corr + e;
                float4 va = *(const float4*)&Vs[kk][sub * 8];
                float4 vb = *(const float4*)&Vs[kk][sub * 8 + 4];
                acc[0] = acc[0] * corr + e * va.x;
                acc[1] = acc[1] * corr + e * va.y;
                acc[2] = acc[2] * corr + e * va.z;
                acc[3] = acc[3] * corr + e * va.w;
                acc[4] = acc[4] * corr + e * vb.x;
                acc[5] = acc[5] * corr + e * vb.y;
                acc[6] = acc[6] * corr + e * vb.z;
                acc[7] = acc[7] * corr + e * vb.w;
                m = nm;
            }
        }
        __syncthreads();
    }

    float inv = 1.f / l;
    float* op = g_att + (size_t)n * EMBED + h * HDIM + sub * 8;
#pragma unroll
    for (int i = 0; i < 8; i++) op[i] = acc[i] * inv;
}

// ---------------- residual + layernorm ----------------
__device__ __forceinline__ float block_reduce_sum(float v) {
    __shared__ float sh[8];
    int lane = threadIdx.x & 31, w = threadIdx.x >> 5;
#pragma unroll
    for (int o = 16; o; o >>= 1) v += __shfl_xor_sync(0xffffffffu, v, o);
    if (!lane) sh[w] = v;
    __syncthreads();
    if (w == 0) {
        v = (lane < 8) ? sh[lane] : 0.f;
#pragma unroll
        for (int o = 4; o; o >>= 1) v += __shfl_xor_sync(0xffffffffu, v, o);
        if (!lane) sh[0] = v;
    }
    __syncthreads();
    float r = sh[0];
    __syncthreads();
    return r;
}

__global__ __launch_bounds__(256) void ln_kernel(
    const float* __restrict__ A, const float* __restrict__ R,
    const float* __restrict__ g, const float* __restrict__ b,
    float* __restrict__ out) {
    int row = blockIdx.x;
    int tid = threadIdx.x;
    const float* a = A + (size_t)row * EMBED;
    const float* r = R + (size_t)row * EMBED;
    float x[4];
    float s = 0.f;
#pragma unroll
    for (int i = 0; i < 4; i++) {
        x[i] = a[tid + i * 256] + r[tid + i * 256];
        s += x[i];
    }
    float mu = block_reduce_sum(s) * (1.0f / EMBED);
    float sq = 0.f;
#pragma unroll
    for (int i = 0; i < 4; i++) {
        float d = x[i] - mu;
        sq += d * d;
    }
    float var = block_reduce_sum(sq) * (1.0f / EMBED);
    float inv = rsqrtf(var + 1e-5f);
#pragma unroll
    for (int i = 0; i < 4; i++) {
        int c = tid + i * 256;
        out[(size_t)row * EMBED + c] = (x[i] - mu) * inv * g[c] + b[c];
    }
}

// ---------------- launch ----------------
extern "C" void kernel_launch(void* const* d_in, const int* in_sizes, int n_in,
                              void* d_out, int out_size) {
    const float* coords   = (const float*)d_in[0];
    const float* feats    = (const float*)d_in[1];
    const int*   cu       = (const int*)  d_in[2];
    const float* Wqkv     = (const float*)d_in[3];
    const float* bqkv     = (const float*)d_in[4];
    const float* Wo       = (const float*)d_in[5];
    const float* bo       = (const float*)d_in[6];
    const float* inv_freq = (const float*)d_in[7];
    const float* ln1_g    = (const float*)d_in[8];
    const float* ln1_b    = (const float*)d_in[9];
    const float* W1       = (const float*)d_in[10];
    const float* b1       = (const float*)d_in[11];
    const float* W2       = (const float*)d_in[12];
    const float* b2       = (const float*)d_in[13];
    const float* ln2_g    = (const float*)d_in[14];
    const float* ln2_b    = (const float*)d_in[15];
    float* out = (float*)d_out;

    float *p_qkv, *p_att, *p_o, *p_h, *p_f1, *p_f2;
    cudaGetSymbolAddress((void**)&p_qkv, g_qkv);
    cudaGetSymbolAddress((void**)&p_att, g_att);
    cudaGetSymbolAddress((void**)&p_o,   g_o);
    cudaGetSymbolAddress((void**)&p_h,   g_h);
    cudaGetSymbolAddress((void**)&p_f1,  g_f1);
    cudaGetSymbolAddress((void**)&p_f2,  g_f2);

    // 1. segments
    seg_kernel<<<(N_TOK + 255) / 256, 256>>>(cu);

    // 2. qkv = feats @ Wqkv + bqkv   [4096 x 3072]
    tf32gemm_kernel<0><<<dim3(QKV3 / 128, N_TOK / 128), 256>>>(feats, Wqkv, bqkv, p_qkv,
                                                               N_TOK, QKV3, EMBED);
    // 3. rope on q,k
    rope_kernel<<<(N_TOK * NHEAD * 32 + 255) / 256, 256>>>(coords, inv_freq);

    // 4. attention -> g_att
    attn_kernel<<<dim3(N_TOK / 32, NHEAD), 256>>>();

    // 5. o = att @ Wo + bo
    tf32gemm_kernel<0><<<dim3(EMBED / 128, N_TOK / 128), 256>>>(p_att, Wo, bo, p_o,
                                                                N_TOK, EMBED, EMBED);
    // 6. h = LN1(feats + o)
    ln_kernel<<<N_TOK, 256>>>(feats, p_o, ln1_g, ln1_b, p_h);

    // 7. f1 = gelu(h @ W1 + b1)
    tf32gemm_kernel<1><<<dim3(FFN / 128, N_TOK / 128), 256>>>(p_h, W1, b1, p_f1,
                                                              N_TOK, FFN, EMBED);
    // 8. f2 = f1 @ W2 + b2
    tf32gemm_kernel<0><<<dim3(EMBED / 128, N_TOK / 128), 256>>>(p_f1, W2, b2, p_f2,
                                                                N_TOK, EMBED, FFN);
    // 9. out = LN2(h + f2)
    ln_kernel<<<N_TOK, 256>>>(p_h, p_f2, ln2_g, ln2_b, out);
}

// round 7
// speedup vs baseline: 1.5484x; 1.0287x over previous
#include <cuda_runtime.h>
#include <cstdint>

#define N_TOK 4096
#define EMBED 1024
#define NHEAD 16
#define HDIM 64
#define FFN 4096
#define QKV3 3072

// ---------------- scratch (device globals; no allocation) ----------------
__device__ float g_qkv[N_TOK * QKV3];       // [n][3][16][64]
__device__ float g_att[N_TOK * EMBED];      // attention output (n, h*64+d)
__device__ float g_o  [N_TOK * EMBED];      // after Wo
__device__ float g_h  [N_TOK * EMBED];      // LN1 output
__device__ float g_f1 [N_TOK * FFN];        // gelu(h@W1+b1)
__device__ float g_f2 [N_TOK * EMBED];      // f1@W2+b2
__device__ int   g_seg[N_TOK];
__device__ int   g_segstart[N_TOK];
__device__ int   g_segend[N_TOK];

// ---------------- segment ids ----------------
__global__ void seg_kernel(const int* __restrict__ cu) {
    int n = blockIdx.x * blockDim.x + threadIdx.x;
    if (n >= N_TOK) return;
    int s = 0;
#pragma unroll
    for (int i = 1; i <= 8; i++) s += (cu[i] <= n) ? 1 : 0;
    g_seg[n] = s;
    g_segstart[n] = cu[s];
    g_segend[n] = cu[s + 1];
}

// ---------------- RoPE on q and k ----------------
__global__ void rope_kernel(const float* __restrict__ coords,
                            const float* __restrict__ invf) {
    int idx = blockIdx.x * blockDim.x + threadIdx.x;
    if (idx >= N_TOK * NHEAD * 32) return;
    int j = idx & 31;
    int h = (idx >> 5) & 15;
    int n = idx >> 9;
    float ang = coords[n * 4 + (j >> 3)] * invf[j];
    float s, c;
    sincosf(ang, &s, &c);
    size_t base = (size_t)n * QKV3 + h * HDIM;
#pragma unroll
    for (int part = 0; part < 2; part++) {
        float* p = g_qkv + base + part * EMBED;
        float x1 = p[j], x2 = p[j + 32];
        p[j]      = x1 * c - x2 * s;
        p[j + 32] = x2 * c + x1 * s;
    }
}

// ---------------- TF32 tensor-core GEMM (fragment-major smem) ----------
// C[M,N] = A[M,K] @ B[K,N] + bias, optional gelu.
// 128x128 block tile, BK=16, 256 threads (8 warps), warp tile 64x32.
//
// A fragment storage: per (kc in 2, mb=m/16 in 8): 128-word block.
//   element A[m][k] (mb=m>>4, r8=(m>>3)&1, g=m&7; kc=k>>3, t=k&3, h=(k>>2)&1)
//   at word (4*g + (t ^ (g>>1)))*4 + 2*h + r8.
//   Consumer lane (g,t) does ONE LDS.128 at (4*g + (t^(g>>1)))*4 and gets
//   [a0,a1,a2,a3] in exactly the m16n8k8 order. XOR makes stage STS <=2-way.
// B fragment storage: per (kc in 2, nb=n/8 in 16): 66-word block (64 used;
//   stride 66 breaks write bank aliasing).
//   element B[k][n] (nb=n>>3, gn=n&7) at word (gn*4 + t)*2 + h.
//   Consumer lane does ONE LDS.64 at lane*2 -> [b0,b1].

__device__ __forceinline__ float gelu_f(float x) {
    float x3 = x * x * x;
    return 0.5f * x * (1.0f + tanhf(0.7978845608028654f * (x + 0.044715f * x3)));
}

__device__ __forceinline__ uint32_t f2tf(float f) {
    uint32_t u;
    asm("cvt.rna.tf32.f32 %0, %1;" : "=r"(u) : "f"(f));
    return u;
}

__device__ __forceinline__ void mma_tf32(float c[4], const uint32_t a[4], const uint32_t b[2]) {
    asm volatile(
        "mma.sync.aligned.m16n8k8.row.col.f32.tf32.tf32.f32 "
        "{%0,%1,%2,%3}, {%4,%5,%6,%7}, {%8,%9}, {%0,%1,%2,%3};\n"
        : "+f"(c[0]), "+f"(c[1]), "+f"(c[2]), "+f"(c[3])
        : "r"(a[0]), "r"(a[1]), "r"(a[2]), "r"(a[3]), "r"(b[0]), "r"(b[1]));
}

template <int ACT>
__global__ __launch_bounds__(256, 2) void tf32gemm_kernel(
    const float* __restrict__ A, const float* __restrict__ B,
    const float* __restrict__ bias, float* __restrict__ C,
    int M, int N, int K) {
    __shared__ uint32_t As[2][2][8][128];    // [buf][kc][mb][frag block]
    __shared__ uint32_t Bs[2][2][16][66];    // [buf][kc][nb][frag block]

    int tid = threadIdx.x;
    int bm = blockIdx.y * 128;
    int bn = blockIdx.x * 128;

    int warp = tid >> 5;
    int lane = tid & 31;
    int g = lane >> 2;     // 0..7
    int t = lane & 3;      // 0..3
    int am = (warp & 1) * 4;       // A mb base for this warp (4 blocks)
    int bnb = (warp >> 1) * 4;     // B nb base for this warp (4 blocks)
    int warp_m = (warp & 1) * 64;
    int warp_n = (warp >> 1) * 32;

    // consumer fragment offsets within blocks
    int a_off = 16 * g + ((t ^ (g >> 1)) << 2);   // word offset, 16B aligned
    int b_off = lane * 2;                          // word offset, 8B aligned

    // staging mapping: A -> thread owns row m=tid>>1, k-chunk kc=tid&1
    int sA_m = tid >> 1;
    int sA_kc = tid & 1;
    int sA_mb = sA_m >> 4;
    int sA_r8 = (sA_m >> 3) & 1;
    int sA_g = sA_m & 7;
    int sA_gx = sA_g >> 1;
    // B -> thread owns row k=tid>>4, n block nb=tid&15
    int sB_k = tid >> 4;
    int sB_nb = tid & 15;
    int sB_kc = sB_k >> 3;
    int sB_t = sB_k & 3;
    int sB_h = (sB_k >> 2) & 1;

    const float* Ag = A + (size_t)(bm + sA_m) * K + sA_kc * 8;
    const float* Bg = B + (size_t)sB_k * N + bn + sB_nb * 8;

    float acc[4][4][4];
#pragma unroll
    for (int i = 0; i < 4; i++)
#pragma unroll
        for (int j = 0; j < 4; j++)
#pragma unroll
            for (int r = 0; r < 4; r++) acc[i][j][r] = 0.f;

    float ra[8], rb[8];

    // prologue: load tile 0
    {
        float4 v0 = *(const float4*)Ag;
        float4 v1 = *(const float4*)(Ag + 4);
        ra[0]=v0.x; ra[1]=v0.y; ra[2]=v0.z; ra[3]=v0.w;
        ra[4]=v1.x; ra[5]=v1.y; ra[6]=v1.z; ra[7]=v1.w;
        float4 w0 = *(const float4*)Bg;
        float4 w1 = *(const float4*)(Bg + 4);
        rb[0]=w0.x; rb[1]=w0.y; rb[2]=w0.z; rb[3]=w0.w;
        rb[4]=w1.x; rb[5]=w1.y; rb[6]=w1.z; rb[7]=w1.w;
    }
    {
        uint32_t* ab = &As[0][sA_kc][sA_mb][0];
#pragma unroll
        for (int kk = 0; kk < 8; kk++) {
            int tt = kk & 3, hh = kk >> 2;
            ab[16 * sA_g + ((tt ^ sA_gx) << 2) + (hh << 1) + sA_r8] = f2tf(ra[kk]);
        }
        uint32_t* bb = &Bs[0][sB_kc][sB_nb][0];
#pragma unroll
        for (int gn = 0; gn < 8; gn++) {
            bb[(gn * 4 + sB_t) * 2 + sB_h] = f2tf(rb[gn]);
        }
    }
    __syncthreads();

    int nk = K >> 4;
    for (int kt = 0; kt < nk; kt++) {
        int cur = kt & 1;
        if (kt + 1 < nk) {
            const float* Ap = Ag + (kt + 1) * 16;
            const float* Bp = Bg + (size_t)(kt + 1) * 16 * N;
            float4 v0 = *(const float4*)Ap;
            float4 v1 = *(const float4*)(Ap + 4);
            ra[0]=v0.x; ra[1]=v0.y; ra[2]=v0.z; ra[3]=v0.w;
            ra[4]=v1.x; ra[5]=v1.y; ra[6]=v1.z; ra[7]=v1.w;
            float4 w0 = *(const float4*)Bp;
            float4 w1 = *(const float4*)(Bp + 4);
            rb[0]=w0.x; rb[1]=w0.y; rb[2]=w0.z; rb[3]=w0.w;
            rb[4]=w1.x; rb[5]=w1.y; rb[6]=w1.z; rb[7]=w1.w;
        }

#pragma unroll
        for (int kc = 0; kc < 2; kc++) {
            uint32_t af[4][4];
            uint32_t bf[4][2];
#pragma unroll
            for (int i = 0; i < 4; i++) {
                uint4 v = *(const uint4*)&As[cur][kc][am + i][a_off];
                af[i][0] = v.x; af[i][1] = v.y; af[i][2] = v.z; af[i][3] = v.w;
            }
#pragma unroll
            for (int j = 0; j < 4; j++) {
                uint2 v = *(const uint2*)&Bs[cur][kc][bnb + j][b_off];
                bf[j][0] = v.x; bf[j][1] = v.y;
            }
#pragma unroll
            for (int i = 0; i < 4; i++)
#pragma unroll
                for (int j = 0; j < 4; j++)
                    mma_tf32(acc[i][j], af[i], bf[j]);
        }

        if (kt + 1 < nk) {
            int nxt = cur ^ 1;
            uint32_t* ab = &As[nxt][sA_kc][sA_mb][0];
#pragma unroll
            for (int kk = 0; kk < 8; kk++) {
                int tt = kk & 3, hh = kk >> 2;
                ab[16 * sA_g + ((tt ^ sA_gx) << 2) + (hh << 1) + sA_r8] = f2tf(ra[kk]);
            }
            uint32_t* bb2 = &Bs[nxt][sB_kc][sB_nb][0];
#pragma unroll
            for (int gn = 0; gn < 8; gn++) {
                bb2[(gn * 4 + sB_t) * 2 + sB_h] = f2tf(rb[gn]);
            }
        }
        __syncthreads();
    }

    // epilogue: bias (+gelu) and store
#pragma unroll
    for (int j = 0; j < 4; j++) {
        int col = bn + warp_n + j * 8 + 2 * t;
        float2 bb = *(const float2*)(bias + col);
#pragma unroll
        for (int i = 0; i < 4; i++) {
            int r = bm + warp_m + i * 16 + g;
            float x0 = acc[i][j][0] + bb.x;
            float x1 = acc[i][j][1] + bb.y;
            float x2 = acc[i][j][2] + bb.x;
            float x3 = acc[i][j][3] + bb.y;
            if (ACT == 1) {
                x0 = gelu_f(x0); x1 = gelu_f(x1);
                x2 = gelu_f(x2); x3 = gelu_f(x3);
            }
            *(float2*)(C + (size_t)r * N + col)       = make_float2(x0, x1);
            *(float2*)(C + (size_t)(r + 8) * N + col) = make_float2(x2, x3);
        }
    }
}

// ---------------- attention: block = (32-query tile, head) ----------------
__global__ __launch_bounds__(256) void attn_kernel() {
    __shared__ float Ks[32][64];
    __shared__ float Vs[32][64];
    __shared__ int   Sg[32];

    int h = blockIdx.y;
    int n0 = blockIdx.x * 32;
    int tid = threadIdx.x;
    int ql = tid >> 3;    // 0..31 query within tile (also key row loaded)
    int sub = tid & 7;    // 0..7 dim group
    int n = n0 + ql;
    int my_seg = g_seg[n];

    const float scale = 0.125f;  // 1/sqrt(64)
    float q[8];
    const float* qp = g_qkv + (size_t)n * QKV3 + h * HDIM + sub * 8;
#pragma unroll
    for (int i = 0; i < 8; i++) q[i] = qp[i] * scale;

    float m = -1e30f, l = 0.f;
    float acc[8];
#pragma unroll
    for (int i = 0; i < 8; i++) acc[i] = 0.f;

    int k_lo = g_segstart[n0];
    int k_hi = g_segend[n0 + 31];

    for (int kt = k_lo; kt < k_hi; kt += 32) {
        int key = kt + ql;
        if (key < k_hi) {
            const float* kp = g_qkv + (size_t)key * QKV3 + EMBED + h * HDIM + sub * 8;
            *(float4*)&Ks[ql][sub * 8]     = *(const float4*)kp;
            *(float4*)&Ks[ql][sub * 8 + 4] = *(const float4*)(kp + 4);
            const float* vp = kp + EMBED;
            *(float4*)&Vs[ql][sub * 8]     = *(const float4*)vp;
            *(float4*)&Vs[ql][sub * 8 + 4] = *(const float4*)(vp + 4);
            if (sub == 0) Sg[ql] = g_seg[key];
        } else {
            *(float4*)&Ks[ql][sub * 8]     = make_float4(0, 0, 0, 0);
            *(float4*)&Ks[ql][sub * 8 + 4] = make_float4(0, 0, 0, 0);
            *(float4*)&Vs[ql][sub * 8]     = make_float4(0, 0, 0, 0);
            *(float4*)&Vs[ql][sub * 8 + 4] = make_float4(0, 0, 0, 0);
            if (sub == 0) Sg[ql] = -1;
        }
        __syncthreads();

        int kmax = min(32, k_hi - kt);
        for (int kk = 0; kk < kmax; kk++) {
            float4 ka = *(const float4*)&Ks[kk][sub * 8];
            float4 kb = *(const float4*)&Ks[kk][sub * 8 + 4];
            float p = q[0] * ka.x + q[1] * ka.y + q[2] * ka.z + q[3] * ka.w +
                      q[4] * kb.x + q[5] * kb.y + q[6] * kb.z + q[7] * kb.w;
            p += __shfl_xor_sync(0xffffffffu, p, 1);
            p += __shfl_xor_sync(0xffffffffu, p, 2);
            p += __shfl_xor_sync(0xffffffffu, p, 4);
            if (Sg[kk] == my_seg) {
                float nm = fmaxf(m, p);
                float corr = __expf(m - nm);
                float e = __expf(p - nm);
                l = l * corr + e;
                float4 va = *(const float4*)&Vs[kk][sub * 8];
                float4 vb = *(const float4*)&Vs[kk][sub * 8 + 4];
                acc[0] = acc[0] * corr + e * va.x;
                acc[1] = acc[1] * corr + e * va.y;
                acc[2] = acc[2] * corr + e * va.z;
                acc[3] = acc[3] * corr + e * va.w;
                acc[4] = acc[4] * corr + e * vb.x;
                acc[5] = acc[5] * corr + e * vb.y;
                acc[6] = acc[6] * corr + e * vb.z;
                acc[7] = acc[7] * corr + e * vb.w;
                m = nm;
            }
        }
        __syncthreads();
    }

    float inv = 1.f / l;
    float* op = g_att + (size_t)n * EMBED + h * HDIM + sub * 8;
#pragma unroll
    for (int i = 0; i < 8; i++) op[i] = acc[i] * inv;
}

// ---------------- residual + layernorm ----------------
__device__ __forceinline__ float block_reduce_sum(float v) {
    __shared__ float sh[8];
    int lane = threadIdx.x & 31, w = threadIdx.x >> 5;
#pragma unroll
    for (int o = 16; o; o >>= 1) v += __shfl_xor_sync(0xffffffffu, v, o);
    if (!lane) sh[w] = v;
    __syncthreads();
    if (w == 0) {
        v = (lane < 8) ? sh[lane] : 0.f;
#pragma unroll
        for (int o = 4; o; o >>= 1) v += __shfl_xor_sync(0xffffffffu, v, o);
        if (!lane) sh[0] = v;
    }
    __syncthreads();
    float r = sh[0];
    __syncthreads();
    return r;
}

__global__ __launch_bounds__(256) void ln_kernel(
    const float* __restrict__ A, const float* __restrict__ R,
    const float* __restrict__ g, const float* __restrict__ b,
    float* __restrict__ out) {
    int row = blockIdx.x;
    int tid = threadIdx.x;
    const float* a = A + (size_t)row * EMBED;
    const float* r = R + (size_t)row * EMBED;
    float x[4];
    float s = 0.f;
#pragma unroll
    for (int i = 0; i < 4; i++) {
        x[i] = a[tid + i * 256] + r[tid + i * 256];
        s += x[i];
    }
    float mu = block_reduce_sum(s) * (1.0f / EMBED);
    float sq = 0.f;
#pragma unroll
    for (int i = 0; i < 4; i++) {
        float d = x[i] - mu;
        sq += d * d;
    }
    float var = block_reduce_sum(sq) * (1.0f / EMBED);
    float inv = rsqrtf(var + 1e-5f);
#pragma unroll
    for (int i = 0; i < 4; i++) {
        int c = tid + i * 256;
        out[(size_t)row * EMBED + c] = (x[i] - mu) * inv * g[c] + b[c];
    }
}

// ---------------- launch ----------------
extern "C" void kernel_launch(void* const* d_in, const int* in_sizes, int n_in,
                              void* d_out, int out_size) {
    const float* coords   = (const float*)d_in[0];
    const float* feats    = (const float*)d_in[1];
    const int*   cu       = (const int*)  d_in[2];
    const float* Wqkv     = (const float*)d_in[3];
    const float* bqkv     = (const float*)d_in[4];
    const float* Wo       = (const float*)d_in[5];
    const float* bo       = (const float*)d_in[6];
    const float* inv_freq = (const float*)d_in[7];
    const float* ln1_g    = (const float*)d_in[8];
    const float* ln1_b    = (const float*)d_in[9];
    const float* W1       = (const float*)d_in[10];
    const float* b1       = (const float*)d_in[11];
    const float* W2       = (const float*)d_in[12];
    const float* b2       = (const float*)d_in[13];
    const float* ln2_g    = (const float*)d_in[14];
    const float* ln2_b    = (const float*)d_in[15];
    float* out = (float*)d_out;

    float *p_qkv, *p_att, *p_o, *p_h, *p_f1, *p_f2;
    cudaGetSymbolAddress((void**)&p_qkv, g_qkv);
    cudaGetSymbolAddress((void**)&p_att, g_att);
    cudaGetSymbolAddress((void**)&p_o,   g_o);
    cudaGetSymbolAddress((void**)&p_h,   g_h);
    cudaGetSymbolAddress((void**)&p_f1,  g_f1);
    cudaGetSymbolAddress((void**)&p_f2,  g_f2);

    // 1. segments
    seg_kernel<<<(N_TOK + 255) / 256, 256>>>(cu);

    // 2. qkv = feats @ Wqkv + bqkv   [4096 x 3072]
    tf32gemm_kernel<0><<<dim3(QKV3 / 128, N_TOK / 128), 256>>>(feats, Wqkv, bqkv, p_qkv,
                                                               N_TOK, QKV3, EMBED);
    // 3. rope on q,k
    rope_kernel<<<(N_TOK * NHEAD * 32 + 255) / 256, 256>>>(coords, inv_freq);

    // 4. attention -> g_att
    attn_kernel<<<dim3(N_TOK / 32, NHEAD), 256>>>();

    // 5. o = att @ Wo + bo
    tf32gemm_kernel<0><<<dim3(EMBED / 128, N_TOK / 128), 256>>>(p_att, Wo, bo, p_o,
                                                                N_TOK, EMBED, EMBED);
    // 6. h = LN1(feats + o)
    ln_kernel<<<N_TOK, 256>>>(feats, p_o, ln1_g, ln1_b, p_h);

    // 7. f1 = gelu(h @ W1 + b1)
    tf32gemm_kernel<1><<<dim3(FFN / 128, N_TOK / 128), 256>>>(p_h, W1, b1, p_f1,
                                                              N_TOK, FFN, EMBED);
    // 8. f2 = f1 @ W2 + b2
    tf32gemm_kernel<0><<<dim3(EMBED / 128, N_TOK / 128), 256>>>(p_f1, W2, b2, p_f2,
                                                                N_TOK, EMBED, FFN);
    // 9. out = LN2(h + f2)
    ln_kernel<<<N_TOK, 256>>>(p_h, p_f2, ln2_g, ln2_b, out);
}

// round 8
// speedup vs baseline: 2.3615x; 1.5251x over previous
#include <cuda_runtime.h>
#include <cstdint>

#define N_TOK 4096
#define EMBED 1024
#define NHEAD 16
#define HDIM 64
#define FFN 4096
#define QKV3 3072

// ---------------- scratch (device globals; no allocation) ----------------
__device__ float g_qkv[N_TOK * QKV3];       // [n][3][16][64]
__device__ float g_att[N_TOK * EMBED];      // attention output (n, h*64+d)
__device__ float g_o  [N_TOK * EMBED];      // after Wo
__device__ float g_h  [N_TOK * EMBED];      // LN1 output
__device__ float g_f1 [N_TOK * FFN];        // gelu(h@W1+b1)
__device__ float g_f2 [N_TOK * EMBED];      // f1@W2+b2
__device__ int   g_seg[N_TOK];
__device__ int   g_segstart[N_TOK];
__device__ int   g_segend[N_TOK];

// ---------------- segment ids ----------------
__global__ void seg_kernel(const int* __restrict__ cu) {
    int n = blockIdx.x * blockDim.x + threadIdx.x;
    if (n >= N_TOK) return;
    int s = 0;
#pragma unroll
    for (int i = 1; i <= 8; i++) s += (cu[i] <= n) ? 1 : 0;
    g_seg[n] = s;
    g_segstart[n] = cu[s];
    g_segend[n] = cu[s + 1];
}

// ---------------- RoPE on q and k ----------------
__global__ void rope_kernel(const float* __restrict__ coords,
                            const float* __restrict__ invf) {
    int idx = blockIdx.x * blockDim.x + threadIdx.x;
    if (idx >= N_TOK * NHEAD * 32) return;
    int j = idx & 31;
    int h = (idx >> 5) & 15;
    int n = idx >> 9;
    float ang = coords[n * 4 + (j >> 3)] * invf[j];
    float s, c;
    sincosf(ang, &s, &c);
    size_t base = (size_t)n * QKV3 + h * HDIM;
#pragma unroll
    for (int part = 0; part < 2; part++) {
        float* p = g_qkv + base + part * EMBED;
        float x1 = p[j], x2 = p[j + 32];
        p[j]      = x1 * c - x2 * s;
        p[j + 32] = x2 * c + x1 * s;
    }
}

// ---------------- shared mma helpers ----------------
__device__ __forceinline__ float gelu_f(float x) {
    float x3 = x * x * x;
    return 0.5f * x * (1.0f + tanhf(0.7978845608028654f * (x + 0.044715f * x3)));
}

__device__ __forceinline__ uint32_t f2tf(float f) {
    uint32_t u;
    asm("cvt.rna.tf32.f32 %0, %1;" : "=r"(u) : "f"(f));
    return u;
}

__device__ __forceinline__ void mma_tf32(float c[4], const uint32_t a[4], const uint32_t b[2]) {
    asm volatile(
        "mma.sync.aligned.m16n8k8.row.col.f32.tf32.tf32.f32 "
        "{%0,%1,%2,%3}, {%4,%5,%6,%7}, {%8,%9}, {%0,%1,%2,%3};\n"
        : "+f"(c[0]), "+f"(c[1]), "+f"(c[2]), "+f"(c[3])
        : "r"(a[0]), "r"(a[1]), "r"(a[2]), "r"(a[3]), "r"(b[0]), "r"(b[1]));
}

// ---------------- TF32 tensor-core GEMM (fragment-major smem) ----------
template <int ACT>
__global__ __launch_bounds__(256, 2) void tf32gemm_kernel(
    const float* __restrict__ A, const float* __restrict__ B,
    const float* __restrict__ bias, float* __restrict__ C,
    int M, int N, int K) {
    __shared__ uint32_t As[2][2][8][128];    // [buf][kc][mb][frag block]
    __shared__ uint32_t Bs[2][2][16][66];    // [buf][kc][nb][frag block]

    int tid = threadIdx.x;
    int bm = blockIdx.y * 128;
    int bn = blockIdx.x * 128;

    int warp = tid >> 5;
    int lane = tid & 31;
    int g = lane >> 2;     // 0..7
    int t = lane & 3;      // 0..3
    int am = (warp & 1) * 4;
    int bnb = (warp >> 1) * 4;
    int warp_m = (warp & 1) * 64;
    int warp_n = (warp >> 1) * 32;

    int a_off = 16 * g + ((t ^ (g >> 1)) << 2);
    int b_off = lane * 2;

    int sA_m = tid >> 1;
    int sA_kc = tid & 1;
    int sA_mb = sA_m >> 4;
    int sA_r8 = (sA_m >> 3) & 1;
    int sA_g = sA_m & 7;
    int sA_gx = sA_g >> 1;
    int sB_k = tid >> 4;
    int sB_nb = tid & 15;
    int sB_kc = sB_k >> 3;
    int sB_t = sB_k & 3;
    int sB_h = (sB_k >> 2) & 1;

    const float* Ag = A + (size_t)(bm + sA_m) * K + sA_kc * 8;
    const float* Bg = B + (size_t)sB_k * N + bn + sB_nb * 8;

    float acc[4][4][4];
#pragma unroll
    for (int i = 0; i < 4; i++)
#pragma unroll
        for (int j = 0; j < 4; j++)
#pragma unroll
            for (int r = 0; r < 4; r++) acc[i][j][r] = 0.f;

    float ra[8], rb[8];

    {
        float4 v0 = *(const float4*)Ag;
        float4 v1 = *(const float4*)(Ag + 4);
        ra[0]=v0.x; ra[1]=v0.y; ra[2]=v0.z; ra[3]=v0.w;
        ra[4]=v1.x; ra[5]=v1.y; ra[6]=v1.z; ra[7]=v1.w;
        float4 w0 = *(const float4*)Bg;
        float4 w1 = *(const float4*)(Bg + 4);
        rb[0]=w0.x; rb[1]=w0.y; rb[2]=w0.z; rb[3]=w0.w;
        rb[4]=w1.x; rb[5]=w1.y; rb[6]=w1.z; rb[7]=w1.w;
    }
    {
        uint32_t* ab = &As[0][sA_kc][sA_mb][0];
#pragma unroll
        for (int kk = 0; kk < 8; kk++) {
            int tt = kk & 3, hh = kk >> 2;
            ab[16 * sA_g + ((tt ^ sA_gx) << 2) + (hh << 1) + sA_r8] = f2tf(ra[kk]);
        }
        uint32_t* bb = &Bs[0][sB_kc][sB_nb][0];
#pragma unroll
        for (int gn = 0; gn < 8; gn++) {
            bb[(gn * 4 + sB_t) * 2 + sB_h] = f2tf(rb[gn]);
        }
    }
    __syncthreads();

    int nk = K >> 4;
    for (int kt = 0; kt < nk; kt++) {
        int cur = kt & 1;
        if (kt + 1 < nk) {
            const float* Ap = Ag + (kt + 1) * 16;
            const float* Bp = Bg + (size_t)(kt + 1) * 16 * N;
            float4 v0 = *(const float4*)Ap;
            float4 v1 = *(const float4*)(Ap + 4);
            ra[0]=v0.x; ra[1]=v0.y; ra[2]=v0.z; ra[3]=v0.w;
            ra[4]=v1.x; ra[5]=v1.y; ra[6]=v1.z; ra[7]=v1.w;
            float4 w0 = *(const float4*)Bp;
            float4 w1 = *(const float4*)(Bp + 4);
            rb[0]=w0.x; rb[1]=w0.y; rb[2]=w0.z; rb[3]=w0.w;
            rb[4]=w1.x; rb[5]=w1.y; rb[6]=w1.z; rb[7]=w1.w;
        }

#pragma unroll
        for (int kc = 0; kc < 2; kc++) {
            uint32_t af[4][4];
            uint32_t bf[4][2];
#pragma unroll
            for (int i = 0; i < 4; i++) {
                uint4 v = *(const uint4*)&As[cur][kc][am + i][a_off];
                af[i][0] = v.x; af[i][1] = v.y; af[i][2] = v.z; af[i][3] = v.w;
            }
#pragma unroll
            for (int j = 0; j < 4; j++) {
                uint2 v = *(const uint2*)&Bs[cur][kc][bnb + j][b_off];
                bf[j][0] = v.x; bf[j][1] = v.y;
            }
#pragma unroll
            for (int i = 0; i < 4; i++)
#pragma unroll
                for (int j = 0; j < 4; j++)
                    mma_tf32(acc[i][j], af[i], bf[j]);
        }

        if (kt + 1 < nk) {
            int nxt = cur ^ 1;
            uint32_t* ab = &As[nxt][sA_kc][sA_mb][0];
#pragma unroll
            for (int kk = 0; kk < 8; kk++) {
                int tt = kk & 3, hh = kk >> 2;
                ab[16 * sA_g + ((tt ^ sA_gx) << 2) + (hh << 1) + sA_r8] = f2tf(ra[kk]);
            }
            uint32_t* bb2 = &Bs[nxt][sB_kc][sB_nb][0];
#pragma unroll
            for (int gn = 0; gn < 8; gn++) {
                bb2[(gn * 4 + sB_t) * 2 + sB_h] = f2tf(rb[gn]);
            }
        }
        __syncthreads();
    }

#pragma unroll
    for (int j = 0; j < 4; j++) {
        int col = bn + warp_n + j * 8 + 2 * t;
        float2 bb = *(const float2*)(bias + col);
#pragma unroll
        for (int i = 0; i < 4; i++) {
            int r = bm + warp_m + i * 16 + g;
            float x0 = acc[i][j][0] + bb.x;
            float x1 = acc[i][j][1] + bb.y;
            float x2 = acc[i][j][2] + bb.x;
            float x3 = acc[i][j][3] + bb.y;
            if (ACT == 1) {
                x0 = gelu_f(x0); x1 = gelu_f(x1);
                x2 = gelu_f(x2); x3 = gelu_f(x3);
            }
            *(float2*)(C + (size_t)r * N + col)       = make_float2(x0, x1);
            *(float2*)(C + (size_t)(r + 8) * N + col) = make_float2(x2, x3);
        }
    }
}

// ---------------- flash attention with tf32 mma ----------------
// block = (64 queries, 1 head), 128 threads, 4 warps x 16 query rows.
// K,V tiles of 32 keys staged as tf32 in smem [32][68].
__global__ __launch_bounds__(128) void attn_mma_kernel() {
    __shared__ uint32_t Ks[32][68];
    __shared__ uint32_t Vs[32][68];
    __shared__ uint32_t Ps[4][16][36];
    __shared__ int Sgs[32];

    int h = blockIdx.y;
    int n0 = blockIdx.x * 64;
    int tid = threadIdx.x;
    int warp = tid >> 5, lane = tid & 31;
    int g = lane >> 2, t = lane & 3;
    int q0 = n0 + warp * 16;

    const float scale = 0.125f;   // 1/sqrt(64)

    // Q fragments (persistent in registers), pre-scaled
    uint32_t Qa[8][4];
    {
        const float* qb = g_qkv + h * HDIM;
#pragma unroll
        for (int kc = 0; kc < 8; kc++) {
            int d0 = kc * 8 + t;
            Qa[kc][0] = f2tf(qb[(size_t)(q0 + g) * QKV3 + d0] * scale);
            Qa[kc][1] = f2tf(qb[(size_t)(q0 + g + 8) * QKV3 + d0] * scale);
            Qa[kc][2] = f2tf(qb[(size_t)(q0 + g) * QKV3 + d0 + 4] * scale);
            Qa[kc][3] = f2tf(qb[(size_t)(q0 + g + 8) * QKV3 + d0 + 4] * scale);
        }
    }
    int seg0 = g_seg[q0 + g];
    int seg1 = g_seg[q0 + g + 8];

    float m0 = -1e30f, m1 = -1e30f, l0 = 0.f, l1 = 0.f;
    float O[8][4];
#pragma unroll
    for (int nb = 0; nb < 8; nb++)
#pragma unroll
        for (int c = 0; c < 4; c++) O[nb][c] = 0.f;

    int k_lo = g_segstart[n0];
    int k_hi = g_segend[n0 + 63];

    int skey = tid >> 2, sp = tid & 3;

    for (int kt = k_lo; kt < k_hi; kt += 32) {
        __syncthreads();
        // ---- stage K,V tile (tf32) ----
        {
            int kg = kt + skey;
            if (kg < k_hi) {
                const float* kp = g_qkv + (size_t)kg * QKV3 + EMBED + h * HDIM + sp * 16;
#pragma unroll
                for (int j = 0; j < 4; j++) {
                    float4 v = *(const float4*)(kp + 4 * j);
                    uint4 u = make_uint4(f2tf(v.x), f2tf(v.y), f2tf(v.z), f2tf(v.w));
                    *(uint4*)&Ks[skey][sp * 16 + 4 * j] = u;
                    float4 w = *(const float4*)(kp + EMBED + 4 * j);
                    uint4 u2 = make_uint4(f2tf(w.x), f2tf(w.y), f2tf(w.z), f2tf(w.w));
                    *(uint4*)&Vs[skey][sp * 16 + 4 * j] = u2;
                }
                if (sp == 0) Sgs[skey] = g_seg[kg];
            } else {
                uint4 z = make_uint4(0, 0, 0, 0);
#pragma unroll
                for (int j = 0; j < 4; j++) {
                    *(uint4*)&Ks[skey][sp * 16 + 4 * j] = z;
                    *(uint4*)&Vs[skey][sp * 16 + 4 * j] = z;
                }
                if (sp == 0) Sgs[skey] = -1;
            }
        }
        __syncthreads();

        // ---- scores: S[16 x 32] = Q @ K^T ----
        float S[4][4];
#pragma unroll
        for (int nb = 0; nb < 4; nb++)
#pragma unroll
            for (int c = 0; c < 4; c++) S[nb][c] = 0.f;

#pragma unroll
        for (int kc = 0; kc < 8; kc++) {
#pragma unroll
            for (int nb = 0; nb < 4; nb++) {
                uint32_t b[2];
                b[0] = Ks[nb * 8 + g][kc * 8 + t];
                b[1] = Ks[nb * 8 + g][kc * 8 + t + 4];
                mma_tf32(S[nb], Qa[kc], b);
            }
        }

        // ---- segment mask + online softmax ----
        float mx0 = -1e30f, mx1 = -1e30f;
#pragma unroll
        for (int nb = 0; nb < 4; nb++) {
            int sa = Sgs[nb * 8 + 2 * t];
            int sb = Sgs[nb * 8 + 2 * t + 1];
            S[nb][0] = (sa == seg0) ? S[nb][0] : -1e30f;
            S[nb][1] = (sb == seg0) ? S[nb][1] : -1e30f;
            S[nb][2] = (sa == seg1) ? S[nb][2] : -1e30f;
            S[nb][3] = (sb == seg1) ? S[nb][3] : -1e30f;
            mx0 = fmaxf(mx0, fmaxf(S[nb][0], S[nb][1]));
            mx1 = fmaxf(mx1, fmaxf(S[nb][2], S[nb][3]));
        }
        mx0 = fmaxf(mx0, __shfl_xor_sync(0xffffffffu, mx0, 1));
        mx0 = fmaxf(mx0, __shfl_xor_sync(0xffffffffu, mx0, 2));
        mx1 = fmaxf(mx1, __shfl_xor_sync(0xffffffffu, mx1, 1));
        mx1 = fmaxf(mx1, __shfl_xor_sync(0xffffffffu, mx1, 2));

        float m0n = fmaxf(m0, mx0);
        float m1n = fmaxf(m1, mx1);
        float corr0 = __expf(m0 - m0n);
        float corr1 = __expf(m1 - m1n);
        l0 *= corr0;
        l1 *= corr1;
#pragma unroll
        for (int nb = 0; nb < 8; nb++) {
            O[nb][0] *= corr0; O[nb][1] *= corr0;
            O[nb][2] *= corr1; O[nb][3] *= corr1;
        }
#pragma unroll
        for (int nb = 0; nb < 4; nb++) {
            float p0 = (S[nb][0] == -1e30f) ? 0.f : __expf(S[nb][0] - m0n);
            float p1 = (S[nb][1] == -1e30f) ? 0.f : __expf(S[nb][1] - m0n);
            float p2 = (S[nb][2] == -1e30f) ? 0.f : __expf(S[nb][2] - m1n);
            float p3 = (S[nb][3] == -1e30f) ? 0.f : __expf(S[nb][3] - m1n);
            l0 += p0 + p1;
            l1 += p2 + p3;
            *(uint2*)&Ps[warp][g][nb * 8 + 2 * t]     = make_uint2(f2tf(p0), f2tf(p1));
            *(uint2*)&Ps[warp][g + 8][nb * 8 + 2 * t] = make_uint2(f2tf(p2), f2tf(p3));
        }
        m0 = m0n;
        m1 = m1n;
        __syncwarp();

        // ---- O += P @ V ----
#pragma unroll
        for (int kc2 = 0; kc2 < 4; kc2++) {
            uint32_t Pa[4];
            Pa[0] = Ps[warp][g][kc2 * 8 + t];
            Pa[1] = Ps[warp][g + 8][kc2 * 8 + t];
            Pa[2] = Ps[warp][g][kc2 * 8 + t + 4];
            Pa[3] = Ps[warp][g + 8][kc2 * 8 + t + 4];
#pragma unroll
            for (int nb = 0; nb < 8; nb++) {
                uint32_t b[2];
                b[0] = Vs[kc2 * 8 + t][nb * 8 + g];
                b[1] = Vs[kc2 * 8 + t + 4][nb * 8 + g];
                mma_tf32(O[nb], Pa, b);
            }
        }
    }

    // ---- finalize ----
    l0 += __shfl_xor_sync(0xffffffffu, l0, 1);
    l0 += __shfl_xor_sync(0xffffffffu, l0, 2);
    l1 += __shfl_xor_sync(0xffffffffu, l1, 1);
    l1 += __shfl_xor_sync(0xffffffffu, l1, 2);
    float inv0 = 1.f / l0;
    float inv1 = 1.f / l1;

    float* ob = g_att + h * HDIM;
#pragma unroll
    for (int nb = 0; nb < 8; nb++) {
        int d = nb * 8 + 2 * t;
        *(float2*)&ob[(size_t)(q0 + g) * EMBED + d] =
            make_float2(O[nb][0] * inv0, O[nb][1] * inv0);
        *(float2*)&ob[(size_t)(q0 + g + 8) * EMBED + d] =
            make_float2(O[nb][2] * inv1, O[nb][3] * inv1);
    }
}

// ---------------- residual + layernorm ----------------
__device__ __forceinline__ float block_reduce_sum(float v) {
    __shared__ float sh[8];
    int lane = threadIdx.x & 31, w = threadIdx.x >> 5;
#pragma unroll
    for (int o = 16; o; o >>= 1) v += __shfl_xor_sync(0xffffffffu, v, o);
    if (!lane) sh[w] = v;
    __syncthreads();
    if (w == 0) {
        v = (lane < 8) ? sh[lane] : 0.f;
#pragma unroll
        for (int o = 4; o; o >>= 1) v += __shfl_xor_sync(0xffffffffu, v, o);
        if (!lane) sh[0] = v;
    }
    __syncthreads();
    float r = sh[0];
    __syncthreads();
    return r;
}

__global__ __launch_bounds__(256) void ln_kernel(
    const float* __restrict__ A, const float* __restrict__ R,
    const float* __restrict__ g, const float* __restrict__ b,
    float* __restrict__ out) {
    int row = blockIdx.x;
    int tid = threadIdx.x;
    const float* a = A + (size_t)row * EMBED;
    const float* r = R + (size_t)row * EMBED;
    float x[4];
    float s = 0.f;
#pragma unroll
    for (int i = 0; i < 4; i++) {
        x[i] = a[tid + i * 256] + r[tid + i * 256];
        s += x[i];
    }
    float mu = block_reduce_sum(s) * (1.0f / EMBED);
    float sq = 0.f;
#pragma unroll
    for (int i = 0; i < 4; i++) {
        float d = x[i] - mu;
        sq += d * d;
    }
    float var = block_reduce_sum(sq) * (1.0f / EMBED);
    float inv = rsqrtf(var + 1e-5f);
#pragma unroll
    for (int i = 0; i < 4; i++) {
        int c = tid + i * 256;
        out[(size_t)row * EMBED + c] = (x[i] - mu) * inv * g[c] + b[c];
    }
}

// ---------------- launch ----------------
extern "C" void kernel_launch(void* const* d_in, const int* in_sizes, int n_in,
                              void* d_out, int out_size) {
    const float* coords   = (const float*)d_in[0];
    const float* feats    = (const float*)d_in[1];
    const int*   cu       = (const int*)  d_in[2];
    const float* Wqkv     = (const float*)d_in[3];
    const float* bqkv     = (const float*)d_in[4];
    const float* Wo       = (const float*)d_in[5];
    const float* bo       = (const float*)d_in[6];
    const float* inv_freq = (const float*)d_in[7];
    const float* ln1_g    = (const float*)d_in[8];
    const float* ln1_b    = (const float*)d_in[9];
    const float* W1       = (const float*)d_in[10];
    const float* b1       = (const float*)d_in[11];
    const float* W2       = (const float*)d_in[12];
    const float* b2       = (const float*)d_in[13];
    const float* ln2_g    = (const float*)d_in[14];
    const float* ln2_b    = (const float*)d_in[15];
    float* out = (float*)d_out;

    float *p_qkv, *p_att, *p_o, *p_h, *p_f1, *p_f2;
    cudaGetSymbolAddress((void**)&p_qkv, g_qkv);
    cudaGetSymbolAddress((void**)&p_att, g_att);
    cudaGetSymbolAddress((void**)&p_o,   g_o);
    cudaGetSymbolAddress((void**)&p_h,   g_h);
    cudaGetSymbolAddress((void**)&p_f1,  g_f1);
    cudaGetSymbolAddress((void**)&p_f2,  g_f2);

    // 1. segments
    seg_kernel<<<(N_TOK + 255) / 256, 256>>>(cu);

    // 2. qkv = feats @ Wqkv + bqkv   [4096 x 3072]
    tf32gemm_kernel<0><<<dim3(QKV3 / 128, N_TOK / 128), 256>>>(feats, Wqkv, bqkv, p_qkv,
                                                               N_TOK, QKV3, EMBED);
    // 3. rope on q,k
    rope_kernel<<<(N_TOK * NHEAD * 32 + 255) / 256, 256>>>(coords, inv_freq);

    // 4. attention -> g_att  (flash, tf32 mma)
    attn_mma_kernel<<<dim3(N_TOK / 64, NHEAD), 128>>>();

    // 5. o = att @ Wo + bo
    tf32gemm_kernel<0><<<dim3(EMBED / 128, N_TOK / 128), 256>>>(p_att, Wo, bo, p_o,
                                                                N_TOK, EMBED, EMBED);
    // 6. h = LN1(feats + o)
    ln_kernel<<<N_TOK, 256>>>(feats, p_o, ln1_g, ln1_b, p_h);

    // 7. f1 = gelu(h @ W1 + b1)
    tf32gemm_kernel<1><<<dim3(FFN / 128, N_TOK / 128), 256>>>(p_h, W1, b1, p_f1,
                                                              N_TOK, FFN, EMBED);
    // 8. f2 = f1 @ W2 + b2
    tf32gemm_kernel<0><<<dim3(EMBED / 128, N_TOK / 128), 256>>>(p_f1, W2, b2, p_f2,
                                                                N_TOK, EMBED, FFN);
    // 9. out = LN2(h + f2)
    ln_kernel<<<N_TOK, 256>>>(p_h, p_f2, ln2_g, ln2_b, out);
}

// round 15
// speedup vs baseline: 3.1912x; 1.3513x over previous
#include <cuda_runtime.h>
#include <cuda_bf16.h>
#include <cstdint>

#define N_TOK 4096
#define EMBED 1024
#define NHEAD 16
#define HDIM 64
#define FFN 4096
#define QKV3 3072

// ---------------- scratch (device globals; no allocation) ----------------
__device__ float g_qkv[N_TOK * QKV3];
__device__ float g_o  [N_TOK * EMBED];
__device__ float g_h  [N_TOK * EMBED];
__device__ float g_f2 [N_TOK * EMBED];
__device__ int   g_seg[N_TOK];
__device__ int   g_segstart[N_TOK];
__device__ int   g_segend[N_TOK];
// tf32 (uint32) operand buffers
__device__ uint32_t g_wt  [12582912];   // transposed weights [N][K]: qkv@0, o@3145728, w1@4194304, w2@8388608
__device__ uint32_t g_ftf [N_TOK * EMBED];   // feats tf32
__device__ uint32_t g_atf [N_TOK * EMBED];   // attention out tf32
__device__ uint32_t g_htf [N_TOK * EMBED];   // LN1 out tf32
__device__ uint32_t g_f1tf[N_TOK * FFN];     // gelu(h@W1+b1) tf32

// ---------------- segment ids ----------------
__global__ void seg_kernel(const int* __restrict__ cu) {
    int n = blockIdx.x * blockDim.x + threadIdx.x;
    if (n >= N_TOK) return;
    int s = 0;
#pragma unroll
    for (int i = 1; i <= 8; i++) s += (cu[i] <= n) ? 1 : 0;
    g_seg[n] = s;
    g_segstart[n] = cu[s];
    g_segend[n] = cu[s + 1];
}

// ---------------- RoPE on q and k ----------------
__global__ void rope_kernel(const float* __restrict__ coords,
                            const float* __restrict__ invf) {
    int idx = blockIdx.x * blockDim.x + threadIdx.x;
    if (idx >= N_TOK * NHEAD * 32) return;
    int j = idx & 31;
    int h = (idx >> 5) & 15;
    int n = idx >> 9;
    float ang = coords[n * 4 + (j >> 3)] * invf[j];
    float s, c;
    sincosf(ang, &s, &c);
    size_t base = (size_t)n * QKV3 + h * HDIM;
#pragma unroll
    for (int part = 0; part < 2; part++) {
        float* p = g_qkv + base + part * EMBED;
        float x1 = p[j], x2 = p[j + 32];
        p[j]      = x1 * c - x2 * s;
        p[j + 32] = x2 * c + x1 * s;
    }
}

// ---------------- helpers ----------------
__device__ __forceinline__ float gelu_f(float x) {
    float x3 = x * x * x;
    return 0.5f * x * (1.0f + tanhf(0.7978845608028654f * (x + 0.044715f * x3)));
}
__device__ __forceinline__ uint32_t f2tf(float f) {
    uint32_t u;
    asm("cvt.rna.tf32.f32 %0, %1;" : "=r"(u) : "f"(f));
    return u;
}
__device__ __forceinline__ void mma_tf32(float c[4], const uint32_t a[4], const uint32_t b[2]) {
    asm volatile(
        "mma.sync.aligned.m16n8k8.row.col.f32.tf32.tf32.f32 "
        "{%0,%1,%2,%3}, {%4,%5,%6,%7}, {%8,%9}, {%0,%1,%2,%3};\n"
        : "+f"(c[0]), "+f"(c[1]), "+f"(c[2]), "+f"(c[3])
        : "r"(a[0]), "r"(a[1]), "r"(a[2]), "r"(a[3]), "r"(b[0]), "r"(b[1]));
}
__device__ __forceinline__ uint32_t smem_u32(const void* p) {
    uint32_t a;
    asm("{ .reg .u64 t; cvta.to.shared.u64 t, %1; cvt.u32.u64 %0, t; }" : "=r"(a) : "l"(p));
    return a;
}
__device__ __forceinline__ void ldsm_x4(uint32_t r[4], uint32_t addr) {
    asm volatile("ldmatrix.sync.aligned.m8n8.x4.shared.b16 {%0,%1,%2,%3}, [%4];"
                 : "=r"(r[0]), "=r"(r[1]), "=r"(r[2]), "=r"(r[3]) : "r"(addr));
}
__device__ __forceinline__ void ldsm_x2(uint32_t r[2], uint32_t addr) {
    asm volatile("ldmatrix.sync.aligned.m8n8.x2.shared.b16 {%0,%1}, [%2];"
                 : "=r"(r[0]), "=r"(r[1]) : "r"(addr));
}
#define CP_ASYNC16(dst, src) \
    asm volatile("cp.async.cg.shared.global [%0], [%1], 16;" :: "r"(dst), "l"(src))
#define CP_COMMIT() asm volatile("cp.async.commit_group;" ::: "memory")
#define CP_WAIT2()  asm volatile("cp.async.wait_group 2;" ::: "memory")

// ---------------- operand pre-conversion ----------------
__global__ void xcvt_kernel(const float* __restrict__ src, uint32_t* __restrict__ dst, int n) {
    int i = blockIdx.x * blockDim.x + threadIdx.x;
    if (i < n) dst[i] = f2tf(src[i]);
}
// transpose + cvt: W[K][N] -> T[N][K] tf32
__global__ void wt_kernel(const float* __restrict__ W, uint32_t* __restrict__ T, int K, int N) {
    __shared__ float t[32][33];
    int tx = threadIdx.x, ty = threadIdx.y;
    int n0 = blockIdx.x * 32, k0 = blockIdx.y * 32;
#pragma unroll
    for (int j = 0; j < 32; j += 8)
        t[ty + j][tx] = W[(size_t)(k0 + ty + j) * N + n0 + tx];
    __syncthreads();
#pragma unroll
    for (int j = 0; j < 32; j += 8)
        T[(size_t)(n0 + ty + j) * K + k0 + tx] = f2tf(t[tx][ty + j]);
}

// ---------------- cp.async multistage tf32 GEMM ----------------
// C[M,N] = A[M,K] @ Bt[N][K]^T + bias; A,Bt pre-converted tf32 (uint32).
// 128x128 CTA tile, BK=16, 4 stages, 8 warps (warp tile 64x32), ldmatrix frags.
// smem stage layout (uint32 words): A[m][k]: m*16 + ((k4 ^ ((m>>1)&3))<<2) + (k&3)
//                                   B at +2048 words, same formula with n.
#define GSTAGES 4
#define GSM_BYTES (GSTAGES * 16384)

template <int ACT>
__global__ __launch_bounds__(256, 2) void gemm_cp(
    const uint32_t* __restrict__ A, const uint32_t* __restrict__ Bt,
    const float* __restrict__ bias, void* __restrict__ Cout,
    int M, int N, int K) {
    extern __shared__ uint32_t sm[];
    uint32_t smb = smem_u32(sm);
    int tid = threadIdx.x, warp = tid >> 5, lane = tid & 31;
    int bm = blockIdx.y * 128, bn = blockIdx.x * 128;
    int warp_m = (warp & 1) * 64, warp_n = (warp >> 1) * 32;
    int g = lane >> 2, t = lane & 3;

    // per-lane ldsm byte offsets within a stage
    uint32_t aoff[4][2], boff[4][2];
    {
        int r = lane & 7;
        int qa = lane >> 3;           // 0..3
        int qb = (lane >> 3) & 1;     // 0..1 (lanes 16-31 mirror)
#pragma unroll
        for (int i = 0; i < 4; i++) {
            int ml = warp_m + i * 16 + r + (qa & 1) * 8;
            int sw = (ml >> 1) & 3;
#pragma unroll
            for (int kc = 0; kc < 2; kc++) {
                int k4 = 2 * kc + (qa >> 1);
                aoff[i][kc] = (uint32_t)(ml * 16 + ((k4 ^ sw) << 2)) * 4;
            }
        }
#pragma unroll
        for (int j = 0; j < 4; j++) {
            int nl = warp_n + j * 8 + r;
            int sw = (nl >> 1) & 3;
#pragma unroll
            for (int kc = 0; kc < 2; kc++) {
                int k4 = 2 * kc + qb;
                boff[j][kc] = 8192u + (uint32_t)(nl * 16 + ((k4 ^ sw) << 2)) * 4;
            }
        }
    }

    // staging: thread handles chunks cid = tid, tid+256 for A and for B
    int m0c = tid >> 2, k40 = tid & 3;
    int m1c = (tid + 256) >> 2, k41 = tid & 3;  // (tid+256)&3 == tid&3
    uint32_t adst0 = (uint32_t)(m0c * 16 + ((k40 ^ ((m0c >> 1) & 3)) << 2)) * 4;
    uint32_t adst1 = (uint32_t)(m1c * 16 + ((k41 ^ ((m1c >> 1) & 3)) << 2)) * 4;

    float acc[4][4][4];
#pragma unroll
    for (int i = 0; i < 4; i++)
#pragma unroll
        for (int j = 0; j < 4; j++)
#pragma unroll
            for (int r = 0; r < 4; r++) acc[i][j][r] = 0.f;

    const uint32_t* Ab = A + (size_t)bm * K;
    const uint32_t* Bb = Bt + (size_t)bn * K;
    int nk = K >> 4;

#define ISSUE_STAGE(stg, ktile) do { \
    uint32_t sb_ = smb + (uint32_t)(stg) * 16384u; \
    int kb_ = (ktile) * 16; \
    CP_ASYNC16(sb_ + adst0, Ab + (size_t)m0c * K + kb_ + k40 * 4); \
    CP_ASYNC16(sb_ + adst1, Ab + (size_t)m1c * K + kb_ + k41 * 4); \
    CP_ASYNC16(sb_ + 8192u + adst0, Bb + (size_t)m0c * K + kb_ + k40 * 4); \
    CP_ASYNC16(sb_ + 8192u + adst1, Bb + (size_t)m1c * K + kb_ + k41 * 4); \
} while (0)

    ISSUE_STAGE(0, 0); CP_COMMIT();
    ISSUE_STAGE(1, 1); CP_COMMIT();
    ISSUE_STAGE(2, 2); CP_COMMIT();

    for (int kt = 0; kt < nk; kt++) {
        int s = kt & 3;
        CP_WAIT2();
        __syncthreads();
        if (kt + 3 < nk) ISSUE_STAGE((kt + 3) & 3, kt + 3);
        CP_COMMIT();

        uint32_t sb = smb + (uint32_t)s * 16384u;
#pragma unroll
        for (int kc = 0; kc < 2; kc++) {
            uint32_t af[4][4], bf[4][2];
#pragma unroll
            for (int i = 0; i < 4; i++) ldsm_x4(af[i], sb + aoff[i][kc]);
#pragma unroll
            for (int j = 0; j < 4; j++) ldsm_x2(bf[j], sb + boff[j][kc]);
#pragma unroll
            for (int i = 0; i < 4; i++)
#pragma unroll
                for (int j = 0; j < 4; j++)
                    mma_tf32(acc[i][j], af[i], bf[j]);
        }
    }
#undef ISSUE_STAGE

    // epilogue: bias (+gelu) and store (f32, or tf32 when ACT==1)
#pragma unroll
    for (int j = 0; j < 4; j++) {
        int col = bn + warp_n + j * 8 + 2 * t;
        float2 bb = *(const float2*)(bias + col);
#pragma unroll
        for (int i = 0; i < 4; i++) {
            int r = bm + warp_m + i * 16 + g;
            float x0 = acc[i][j][0] + bb.x;
            float x1 = acc[i][j][1] + bb.y;
            float x2 = acc[i][j][2] + bb.x;
            float x3 = acc[i][j][3] + bb.y;
            if (ACT == 1) {
                x0 = gelu_f(x0); x1 = gelu_f(x1);
                x2 = gelu_f(x2); x3 = gelu_f(x3);
                uint32_t* cp = (uint32_t*)Cout;
                *(uint2*)(cp + (size_t)r * N + col)       = make_uint2(f2tf(x0), f2tf(x1));
                *(uint2*)(cp + (size_t)(r + 8) * N + col) = make_uint2(f2tf(x2), f2tf(x3));
            } else {
                float* cp = (float*)Cout;
                *(float2*)(cp + (size_t)r * N + col)       = make_float2(x0, x1);
                *(float2*)(cp + (size_t)(r + 8) * N + col) = make_float2(x2, x3);
            }
        }
    }
}

// ---------------- flash attention with tf32 mma ----------------
__global__ __launch_bounds__(128) void attn_mma_kernel() {
    __shared__ uint32_t Ks[32][68];
    __shared__ uint32_t Vs[32][68];
    __shared__ uint32_t Ps[4][16][36];
    __shared__ int Sgs[32];

    int h = blockIdx.y;
    int n0 = blockIdx.x * 64;
    int tid = threadIdx.x;
    int warp = tid >> 5, lane = tid & 31;
    int g = lane >> 2, t = lane & 3;
    int q0 = n0 + warp * 16;

    const float scale = 0.125f;

    uint32_t Qa[8][4];
    {
        const float* qb = g_qkv + h * HDIM;
#pragma unroll
        for (int kc = 0; kc < 8; kc++) {
            int d0 = kc * 8 + t;
            Qa[kc][0] = f2tf(qb[(size_t)(q0 + g) * QKV3 + d0] * scale);
            Qa[kc][1] = f2tf(qb[(size_t)(q0 + g + 8) * QKV3 + d0] * scale);
            Qa[kc][2] = f2tf(qb[(size_t)(q0 + g) * QKV3 + d0 + 4] * scale);
            Qa[kc][3] = f2tf(qb[(size_t)(q0 + g + 8) * QKV3 + d0 + 4] * scale);
        }
    }
    int seg0 = g_seg[q0 + g];
    int seg1 = g_seg[q0 + g + 8];

    float m0 = -1e30f, m1 = -1e30f, l0 = 0.f, l1 = 0.f;
    float O[8][4];
#pragma unroll
    for (int nb = 0; nb < 8; nb++)
#pragma unroll
        for (int c = 0; c < 4; c++) O[nb][c] = 0.f;

    int k_lo = g_segstart[n0];
    int k_hi = g_segend[n0 + 63];

    int skey = tid >> 2, sp = tid & 3;

    for (int kt = k_lo; kt < k_hi; kt += 32) {
        __syncthreads();
        {
            int kg = kt + skey;
            if (kg < k_hi) {
                const float* kp = g_qkv + (size_t)kg * QKV3 + EMBED + h * HDIM + sp * 16;
#pragma unroll
                for (int j = 0; j < 4; j++) {
                    float4 v = *(const float4*)(kp + 4 * j);
                    *(uint4*)&Ks[skey][sp * 16 + 4 * j] =
                        make_uint4(f2tf(v.x), f2tf(v.y), f2tf(v.z), f2tf(v.w));
                    float4 w = *(const float4*)(kp + EMBED + 4 * j);
                    *(uint4*)&Vs[skey][sp * 16 + 4 * j] =
                        make_uint4(f2tf(w.x), f2tf(w.y), f2tf(w.z), f2tf(w.w));
                }
                if (sp == 0) Sgs[skey] = g_seg[kg];
            } else {
                uint4 z = make_uint4(0, 0, 0, 0);
#pragma unroll
                for (int j = 0; j < 4; j++) {
                    *(uint4*)&Ks[skey][sp * 16 + 4 * j] = z;
                    *(uint4*)&Vs[skey][sp * 16 + 4 * j] = z;
                }
                if (sp == 0) Sgs[skey] = -1;
            }
        }
        __syncthreads();

        float S[4][4];
#pragma unroll
        for (int nb = 0; nb < 4; nb++)
#pragma unroll
            for (int c = 0; c < 4; c++) S[nb][c] = 0.f;

#pragma unroll
        for (int kc = 0; kc < 8; kc++) {
#pragma unroll
            for (int nb = 0; nb < 4; nb++) {
                uint32_t b[2];
                b[0] = Ks[nb * 8 + g][kc * 8 + t];
                b[1] = Ks[nb * 8 + g][kc * 8 + t + 4];
                mma_tf32(S[nb], Qa[kc], b);
            }
        }

        float mx0 = -1e30f, mx1 = -1e30f;
#pragma unroll
        for (int nb = 0; nb < 4; nb++) {
            int sa = Sgs[nb * 8 + 2 * t];
            int sb = Sgs[nb * 8 + 2 * t + 1];
            S[nb][0] = (sa == seg0) ? S[nb][0] : -1e30f;
            S[nb][1] = (sb == seg0) ? S[nb][1] : -1e30f;
            S[nb][2] = (sa == seg1) ? S[nb][2] : -1e30f;
            S[nb][3] = (sb == seg1) ? S[nb][3] : -1e30f;
            mx0 = fmaxf(mx0, fmaxf(S[nb][0], S[nb][1]));
            mx1 = fmaxf(mx1, fmaxf(S[nb][2], S[nb][3]));
        }
        mx0 = fmaxf(mx0, __shfl_xor_sync(0xffffffffu, mx0, 1));
        mx0 = fmaxf(mx0, __shfl_xor_sync(0xffffffffu, mx0, 2));
        mx1 = fmaxf(mx1, __shfl_xor_sync(0xffffffffu, mx1, 1));
        mx1 = fmaxf(mx1, __shfl_xor_sync(0xffffffffu, mx1, 2));

        float m0n = fmaxf(m0, mx0);
        float m1n = fmaxf(m1, mx1);
        float corr0 = __expf(m0 - m0n);
        float corr1 = __expf(m1 - m1n);
        l0 *= corr0;
        l1 *= corr1;
#pragma unroll
        for (int nb = 0; nb < 8; nb++) {
            O[nb][0] *= corr0; O[nb][1] *= corr0;
            O[nb][2] *= corr1; O[nb][3] *= corr1;
        }
#pragma unroll
        for (int nb = 0; nb < 4; nb++) {
            float p0 = (S[nb][0] == -1e30f) ? 0.f : __expf(S[nb][0] - m0n);
            float p1 = (S[nb][1] == -1e30f) ? 0.f : __expf(S[nb][1] - m0n);
            float p2 = (S[nb][2] == -1e30f) ? 0.f : __expf(S[nb][2] - m1n);
            float p3 = (S[nb][3] == -1e30f) ? 0.f : __expf(S[nb][3] - m1n);
            l0 += p0 + p1;
            l1 += p2 + p3;
            *(uint2*)&Ps[warp][g][nb * 8 + 2 * t]     = make_uint2(f2tf(p0), f2tf(p1));
            *(uint2*)&Ps[warp][g + 8][nb * 8 + 2 * t] = make_uint2(f2tf(p2), f2tf(p3));
        }
        m0 = m0n;
        m1 = m1n;
        __syncwarp();

#pragma unroll
        for (int kc2 = 0; kc2 < 4; kc2++) {
            uint32_t Pa[4];
            Pa[0] = Ps[warp][g][kc2 * 8 + t];
            Pa[1] = Ps[warp][g + 8][kc2 * 8 + t];
            Pa[2] = Ps[warp][g][kc2 * 8 + t + 4];
            Pa[3] = Ps[warp][g + 8][kc2 * 8 + t + 4];
#pragma unroll
            for (int nb = 0; nb < 8; nb++) {
                uint32_t b[2];
                b[0] = Vs[kc2 * 8 + t][nb * 8 + g];
                b[1] = Vs[kc2 * 8 + t + 4][nb * 8 + g];
                mma_tf32(O[nb], Pa, b);
            }
        }
    }

    l0 += __shfl_xor_sync(0xffffffffu, l0, 1);
    l0 += __shfl_xor_sync(0xffffffffu, l0, 2);
    l1 += __shfl_xor_sync(0xffffffffu, l1, 1);
    l1 += __shfl_xor_sync(0xffffffffu, l1, 2);
    float inv0 = 1.f / l0;
    float inv1 = 1.f / l1;

    // write attention output directly as tf32 for the Wo GEMM
    uint32_t* ob = g_atf + h * HDIM;
#pragma unroll
    for (int nb = 0; nb < 8; nb++) {
        int d = nb * 8 + 2 * t;
        *(uint2*)&ob[(size_t)(q0 + g) * EMBED + d] =
            make_uint2(f2tf(O[nb][0] * inv0), f2tf(O[nb][1] * inv0));
        *(uint2*)&ob[(size_t)(q0 + g + 8) * EMBED + d] =
            make_uint2(f2tf(O[nb][2] * inv1), f2tf(O[nb][3] * inv1));
    }
}

// ---------------- residual + layernorm (optional tf32 copy) ----------------
__device__ __forceinline__ float block_reduce_sum(float v) {
    __shared__ float sh[8];
    int lane = threadIdx.x & 31, w = threadIdx.x >> 5;
#pragma unroll
    for (int o = 16; o; o >>= 1) v += __shfl_xor_sync(0xffffffffu, v, o);
    if (!lane) sh[w] = v;
    __syncthreads();
    if (w == 0) {
        v = (lane < 8) ? sh[lane] : 0.f;
#pragma unroll
        for (int o = 4; o; o >>= 1) v += __shfl_xor_sync(0xffffffffu, v, o);
        if (!lane) sh[0] = v;
    }
    __syncthreads();
    float r = sh[0];
    __syncthreads();
    return r;
}

__global__ __launch_bounds__(256) void ln_kernel(
    const float* __restrict__ A, const float* __restrict__ R,
    const float* __restrict__ g, const float* __restrict__ b,
    float* __restrict__ out, uint32_t* __restrict__ outtf) {
    int row = blockIdx.x;
    int tid = threadIdx.x;
    const float* a = A + (size_t)row * EMBED;
    const float* r = R + (size_t)row * EMBED;
    float x[4];
    float s = 0.f;
#pragma unroll
    for (int i = 0; i < 4; i++) {
        x[i] = a[tid + i * 256] + r[tid + i * 256];
        s += x[i];
    }
    float mu = block_reduce_sum(s) * (1.0f / EMBED);
    float sq = 0.f;
#pragma unroll
    for (int i = 0; i < 4; i++) {
        float d = x[i] - mu;
        sq += d * d;
    }
    float var = block_reduce_sum(sq) * (1.0f / EMBED);
    float inv = rsqrtf(var + 1e-5f);
#pragma unroll
    for (int i = 0; i < 4; i++) {
        int c = tid + i * 256;
        float v = (x[i] - mu) * inv * g[c] + b[c];
        out[(size_t)row * EMBED + c] = v;
        if (outtf) outtf[(size_t)row * EMBED + c] = f2tf(v);
    }
}

// ---------------- launch ----------------
extern "C" void kernel_launch(void* const* d_in, const int* in_sizes, int n_in,
                              void* d_out, int out_size) {
    const float* coords   = (const float*)d_in[0];
    const float* feats    = (const float*)d_in[1];
    const int*   cu       = (const int*)  d_in[2];
    const float* Wqkv     = (const float*)d_in[3];
    const float* bqkv     = (const float*)d_in[4];
    const float* Wo       = (const float*)d_in[5];
    const float* bo       = (const float*)d_in[6];
    const float* inv_freq = (const float*)d_in[7];
    const float* ln1_g    = (const float*)d_in[8];
    const float* ln1_b    = (const float*)d_in[9];
    const float* W1       = (const float*)d_in[10];
    const float* b1       = (const float*)d_in[11];
    const float* W2       = (const float*)d_in[12];
    const float* b2       = (const float*)d_in[13];
    const float* ln2_g    = (const float*)d_in[14];
    const float* ln2_b    = (const float*)d_in[15];
    float* out = (float*)d_out;

    float *p_qkv, *p_o, *p_h, *p_f2;
    uint32_t *p_wt, *p_ftf, *p_atf, *p_htf, *p_f1tf;
    cudaGetSymbolAddress((void**)&p_qkv,  g_qkv);
    cudaGetSymbolAddress((void**)&p_o,    g_o);
    cudaGetSymbolAddress((void**)&p_h,    g_h);
    cudaGetSymbolAddress((void**)&p_f2,   g_f2);
    cudaGetSymbolAddress((void**)&p_wt,   g_wt);
    cudaGetSymbolAddress((void**)&p_ftf,  g_ftf);
    cudaGetSymbolAddress((void**)&p_atf,  g_atf);
    cudaGetSymbolAddress((void**)&p_htf,  g_htf);
    cudaGetSymbolAddress((void**)&p_f1tf, g_f1tf);

    const size_t off_qkv = 0;
    const size_t off_o   = 3145728;
    const size_t off_1   = 4194304;
    const size_t off_2   = 8388608;

    cudaFuncSetAttribute(gemm_cp<0>, cudaFuncAttributeMaxDynamicSharedMemorySize, GSM_BYTES);
    cudaFuncSetAttribute(gemm_cp<1>, cudaFuncAttributeMaxDynamicSharedMemorySize, GSM_BYTES);

    // 0. operand pre-conversion
    wt_kernel<<<dim3(QKV3 / 32, EMBED / 32), dim3(32, 8)>>>(Wqkv, p_wt + off_qkv, EMBED, QKV3);
    wt_kernel<<<dim3(EMBED / 32, EMBED / 32), dim3(32, 8)>>>(Wo, p_wt + off_o, EMBED, EMBED);
    wt_kernel<<<dim3(FFN / 32, EMBED / 32), dim3(32, 8)>>>(W1, p_wt + off_1, EMBED, FFN);
    wt_kernel<<<dim3(EMBED / 32, FFN / 32), dim3(32, 8)>>>(W2, p_wt + off_2, FFN, EMBED);
    xcvt_kernel<<<(N_TOK * EMBED + 255) / 256, 256>>>(feats, p_ftf, N_TOK * EMBED);

    // 1. segments
    seg_kernel<<<(N_TOK + 255) / 256, 256>>>(cu);

    // 2. qkv = feats @ Wqkv + bqkv
    gemm_cp<0><<<dim3(QKV3 / 128, N_TOK / 128), 256, GSM_BYTES>>>(
        p_ftf, p_wt + off_qkv, bqkv, p_qkv, N_TOK, QKV3, EMBED);

    // 3. rope
    rope_kernel<<<(N_TOK * NHEAD * 32 + 255) / 256, 256>>>(coords, inv_freq);

    // 4. attention -> g_atf (tf32)
    attn_mma_kernel<<<dim3(N_TOK / 64, NHEAD), 128>>>();

    // 5. o = att @ Wo + bo
    gemm_cp<0><<<dim3(EMBED / 128, N_TOK / 128), 256, GSM_BYTES>>>(
        p_atf, p_wt + off_o, bo, p_o, N_TOK, EMBED, EMBED);

    // 6. h = LN1(feats + o)  (+ tf32 copy)
    ln_kernel<<<N_TOK, 256>>>(feats, p_o, ln1_g, ln1_b, p_h, p_htf);

    // 7. f1 = gelu(h @ W1 + b1) -> tf32 only
    gemm_cp<1><<<dim3(FFN / 128, N_TOK / 128), 256, GSM_BYTES>>>(
        p_htf, p_wt + off_1, b1, p_f1tf, N_TOK, FFN, EMBED);

    // 8. f2 = f1 @ W2 + b2
    gemm_cp<0><<<dim3(EMBED / 128, N_TOK / 128), 256, GSM_BYTES>>>(
        p_f1tf, p_wt + off_2, b2, p_f2, N_TOK, EMBED, FFN);

    // 9. out = LN2(h + f2)
    ln_kernel<<<N_TOK, 256>>>(p_h, p_f2, ln2_g, ln2_b, out, nullptr);
}

// round 17
// speedup vs baseline: 5.2846x; 1.6560x over previous
#include <cuda_runtime.h>
#include <cuda_bf16.h>
#include <cstdint>

#define N_TOK 4096
#define EMBED 1024
#define NHEAD 16
#define HDIM 64
#define FFN 4096
#define QKV3 3072

// ---------------- scratch (device globals; no allocation) ----------------
__device__ float g_qkv[N_TOK * QKV3];
__device__ float g_o  [N_TOK * EMBED];
__device__ float g_h  [N_TOK * EMBED];
__device__ float g_f2 [N_TOK * EMBED];
__device__ int   g_seg[N_TOK];
__device__ int   g_segstart[N_TOK];
__device__ int   g_segend[N_TOK];
// tf32 (uint32) operand buffers
__device__ uint32_t g_wt  [12582912];   // transposed weights [N][K]
__device__ uint32_t g_ftf [N_TOK * EMBED];
__device__ uint32_t g_atf [N_TOK * EMBED];
__device__ uint32_t g_htf [N_TOK * EMBED];
__device__ uint32_t g_f1tf[N_TOK * FFN];
// head-major tf32 q/k/v: [h][n][64]
__device__ uint32_t g_qtf[NHEAD * N_TOK * HDIM];
__device__ uint32_t g_ktf[NHEAD * N_TOK * HDIM];
__device__ uint32_t g_vtf[NHEAD * N_TOK * HDIM];

// ---------------- segment ids ----------------
__global__ void seg_kernel(const int* __restrict__ cu) {
    int n = blockIdx.x * blockDim.x + threadIdx.x;
    if (n >= N_TOK) return;
    int s = 0;
#pragma unroll
    for (int i = 1; i <= 8; i++) s += (cu[i] <= n) ? 1 : 0;
    g_seg[n] = s;
    g_segstart[n] = cu[s];
    g_segend[n] = cu[s + 1];
}

// ---------------- helpers ----------------
__device__ __forceinline__ float gelu_f(float x) {
    float x3 = x * x * x;
    return 0.5f * x * (1.0f + tanhf(0.7978845608028654f * (x + 0.044715f * x3)));
}
__device__ __forceinline__ uint32_t f2tf(float f) {
    uint32_t u;
    asm("cvt.rna.tf32.f32 %0, %1;" : "=r"(u) : "f"(f));
    return u;
}
__device__ __forceinline__ void mma_tf32(float c[4], const uint32_t a[4], const uint32_t b[2]) {
    asm volatile(
        "mma.sync.aligned.m16n8k8.row.col.f32.tf32.tf32.f32 "
        "{%0,%1,%2,%3}, {%4,%5,%6,%7}, {%8,%9}, {%0,%1,%2,%3};\n"
        : "+f"(c[0]), "+f"(c[1]), "+f"(c[2]), "+f"(c[3])
        : "r"(a[0]), "r"(a[1]), "r"(a[2]), "r"(a[3]), "r"(b[0]), "r"(b[1]));
}
__device__ __forceinline__ uint32_t smem_u32(const void* p) {
    uint32_t a;
    asm("{ .reg .u64 t; cvta.to.shared.u64 t, %1; cvt.u32.u64 %0, t; }" : "=r"(a) : "l"(p));
    return a;
}
__device__ __forceinline__ void ldsm_x4(uint32_t r[4], uint32_t addr) {
    asm volatile("ldmatrix.sync.aligned.m8n8.x4.shared.b16 {%0,%1,%2,%3}, [%4];"
                 : "=r"(r[0]), "=r"(r[1]), "=r"(r[2]), "=r"(r[3]) : "r"(addr));
}
__device__ __forceinline__ void ldsm_x2(uint32_t r[2], uint32_t addr) {
    asm volatile("ldmatrix.sync.aligned.m8n8.x2.shared.b16 {%0,%1}, [%2];"
                 : "=r"(r[0]), "=r"(r[1]) : "r"(addr));
}
#define CP_ASYNC16(dst, src) \
    asm volatile("cp.async.cg.shared.global [%0], [%1], 16;" :: "r"(dst), "l"(src))
#define CP_ASYNC16Z(dst, src, vld) \
    asm volatile("cp.async.cg.shared.global [%0], [%1], 16, %2;" :: "r"(dst), "l"(src), "r"(vld))
#define CP_COMMIT() asm volatile("cp.async.commit_group;" ::: "memory")

// ---------------- RoPE + head-major tf32 q/k/v ----------------
__global__ void ropecvt_kernel(const float* __restrict__ coords,
                               const float* __restrict__ invf) {
    int idx = blockIdx.x * blockDim.x + threadIdx.x;
    if (idx >= N_TOK * NHEAD * 32) return;
    int j = idx & 31;
    int h = (idx >> 5) & 15;
    int n = idx >> 9;
    float ang = coords[n * 4 + (j >> 3)] * invf[j];
    float s, c;
    sincosf(ang, &s, &c);
    const float* base = g_qkv + (size_t)n * QKV3 + h * HDIM;
    size_t ob = (size_t)h * N_TOK * HDIM + (size_t)n * HDIM;
    float q1 = base[j], q2 = base[j + 32];
    g_qtf[ob + j]      = f2tf((q1 * c - q2 * s) * 0.125f);
    g_qtf[ob + j + 32] = f2tf((q2 * c + q1 * s) * 0.125f);
    float k1 = base[EMBED + j], k2 = base[EMBED + j + 32];
    g_ktf[ob + j]      = f2tf(k1 * c - k2 * s);
    g_ktf[ob + j + 32] = f2tf(k2 * c + k1 * s);
    g_vtf[ob + j]      = f2tf(base[2 * EMBED + j]);
    g_vtf[ob + j + 32] = f2tf(base[2 * EMBED + j + 32]);
}

// ---------------- operand pre-conversion ----------------
__global__ void xcvt_kernel(const float* __restrict__ src, uint32_t* __restrict__ dst, int n) {
    int i = blockIdx.x * blockDim.x + threadIdx.x;
    if (i < n) dst[i] = f2tf(src[i]);
}
__global__ void wt_kernel(const float* __restrict__ W, uint32_t* __restrict__ T, int K, int N) {
    __shared__ float t[32][33];
    int tx = threadIdx.x, ty = threadIdx.y;
    int n0 = blockIdx.x * 32, k0 = blockIdx.y * 32;
#pragma unroll
    for (int j = 0; j < 32; j += 8)
        t[ty + j][tx] = W[(size_t)(k0 + ty + j) * N + n0 + tx];
    __syncthreads();
#pragma unroll
    for (int j = 0; j < 32; j += 8)
        T[(size_t)(n0 + ty + j) * K + k0 + tx] = f2tf(t[tx][ty + j]);
}

// ---------------- cp.async multistage tf32 GEMM ----------------
#define GSTAGES 4
#define GSM_BYTES (GSTAGES * 16384)

template <int ACT>
__global__ __launch_bounds__(256, 2) void gemm_cp(
    const uint32_t* __restrict__ A, const uint32_t* __restrict__ Bt,
    const float* __restrict__ bias, void* __restrict__ Cout,
    int M, int N, int K) {
    extern __shared__ uint32_t sm[];
    uint32_t smb = smem_u32(sm);
    int tid = threadIdx.x, warp = tid >> 5, lane = tid & 31;
    int bm = blockIdx.y * 128, bn = blockIdx.x * 128;
    int warp_m = (warp & 1) * 64, warp_n = (warp >> 1) * 32;
    int g = lane >> 2, t = lane & 3;

    uint32_t aoff[4][2], boff[4][2];
    {
        int r = lane & 7;
        int qa = lane >> 3;
        int qb = (lane >> 3) & 1;
#pragma unroll
        for (int i = 0; i < 4; i++) {
            int ml = warp_m + i * 16 + r + (qa & 1) * 8;
            int sw = (ml >> 1) & 3;
#pragma unroll
            for (int kc = 0; kc < 2; kc++) {
                int k4 = 2 * kc + (qa >> 1);
                aoff[i][kc] = (uint32_t)(ml * 16 + ((k4 ^ sw) << 2)) * 4;
            }
        }
#pragma unroll
        for (int j = 0; j < 4; j++) {
            int nl = warp_n + j * 8 + r;
            int sw = (nl >> 1) & 3;
#pragma unroll
            for (int kc = 0; kc < 2; kc++) {
                int k4 = 2 * kc + qb;
                boff[j][kc] = 8192u + (uint32_t)(nl * 16 + ((k4 ^ sw) << 2)) * 4;
            }
        }
    }

    int m0c = tid >> 2, k40 = tid & 3;
    int m1c = (tid + 256) >> 2, k41 = tid & 3;
    uint32_t adst0 = (uint32_t)(m0c * 16 + ((k40 ^ ((m0c >> 1) & 3)) << 2)) * 4;
    uint32_t adst1 = (uint32_t)(m1c * 16 + ((k41 ^ ((m1c >> 1) & 3)) << 2)) * 4;

    float acc[4][4][4];
#pragma unroll
    for (int i = 0; i < 4; i++)
#pragma unroll
        for (int j = 0; j < 4; j++)
#pragma unroll
            for (int r = 0; r < 4; r++) acc[i][j][r] = 0.f;

    const uint32_t* Ab = A + (size_t)bm * K;
    const uint32_t* Bb = Bt + (size_t)bn * K;
    int nk = K >> 4;

#define ISSUE_STAGE(stg, ktile) do { \
    uint32_t sb_ = smb + (uint32_t)(stg) * 16384u; \
    int kb_ = (ktile) * 16; \
    CP_ASYNC16(sb_ + adst0, Ab + (size_t)m0c * K + kb_ + k40 * 4); \
    CP_ASYNC16(sb_ + adst1, Ab + (size_t)m1c * K + kb_ + k41 * 4); \
    CP_ASYNC16(sb_ + 8192u + adst0, Bb + (size_t)m0c * K + kb_ + k40 * 4); \
    CP_ASYNC16(sb_ + 8192u + adst1, Bb + (size_t)m1c * K + kb_ + k41 * 4); \
} while (0)

    ISSUE_STAGE(0, 0); CP_COMMIT();
    ISSUE_STAGE(1, 1); CP_COMMIT();
    ISSUE_STAGE(2, 2); CP_COMMIT();

    for (int kt = 0; kt < nk; kt++) {
        int s = kt & 3;
        asm volatile("cp.async.wait_group 2;" ::: "memory");
        __syncthreads();
        if (kt + 3 < nk) ISSUE_STAGE((kt + 3) & 3, kt + 3);
        CP_COMMIT();

        uint32_t sb = smb + (uint32_t)s * 16384u;
#pragma unroll
        for (int kc = 0; kc < 2; kc++) {
            uint32_t af[4][4], bf[4][2];
#pragma unroll
            for (int i = 0; i < 4; i++) ldsm_x4(af[i], sb + aoff[i][kc]);
#pragma unroll
            for (int j = 0; j < 4; j++) ldsm_x2(bf[j], sb + boff[j][kc]);
#pragma unroll
            for (int i = 0; i < 4; i++)
#pragma unroll
                for (int j = 0; j < 4; j++)
                    mma_tf32(acc[i][j], af[i], bf[j]);
        }
    }
#undef ISSUE_STAGE

#pragma unroll
    for (int j = 0; j < 4; j++) {
        int col = bn + warp_n + j * 8 + 2 * t;
        float2 bb = *(const float2*)(bias + col);
#pragma unroll
        for (int i = 0; i < 4; i++) {
            int r = bm + warp_m + i * 16 + g;
            float x0 = acc[i][j][0] + bb.x;
            float x1 = acc[i][j][1] + bb.y;
            float x2 = acc[i][j][2] + bb.x;
            float x3 = acc[i][j][3] + bb.y;
            if (ACT == 1) {
                x0 = gelu_f(x0); x1 = gelu_f(x1);
                x2 = gelu_f(x2); x3 = gelu_f(x3);
                uint32_t* cp = (uint32_t*)Cout;
                *(uint2*)(cp + (size_t)r * N + col)       = make_uint2(f2tf(x0), f2tf(x1));
                *(uint2*)(cp + (size_t)(r + 8) * N + col) = make_uint2(f2tf(x2), f2tf(x3));
            } else {
                float* cp = (float*)Cout;
                *(float2*)(cp + (size_t)r * N + col)       = make_float2(x0, x1);
                *(float2*)(cp + (size_t)(r + 8) * N + col) = make_float2(x2, x3);
            }
        }
    }
}

// ---------------- flash attention: tf32 mma + cp.async double buffer ------
__global__ __launch_bounds__(128) void attn_mma_kernel() {
    __shared__ uint32_t Ks[2][32][68];
    __shared__ uint32_t Vs[2][32][68];
    __shared__ uint32_t Ps[4][16][36];
    __shared__ int Sgs[2][32];

    int h = blockIdx.y;
    int n0 = blockIdx.x * 64;
    int tid = threadIdx.x;
    int warp = tid >> 5, lane = tid & 31;
    int g = lane >> 2, t = lane & 3;
    int q0 = n0 + warp * 16;

    const uint32_t* qb = g_qtf + (size_t)h * N_TOK * HDIM;
    const uint32_t* kb = g_ktf + (size_t)h * N_TOK * HDIM;
    const uint32_t* vb = g_vtf + (size_t)h * N_TOK * HDIM;

    // Q fragments (pre-scaled tf32)
    uint32_t Qa[8][4];
#pragma unroll
    for (int kc = 0; kc < 8; kc++) {
        int d0 = kc * 8 + t;
        Qa[kc][0] = qb[(size_t)(q0 + g) * HDIM + d0];
        Qa[kc][1] = qb[(size_t)(q0 + g + 8) * HDIM + d0];
        Qa[kc][2] = qb[(size_t)(q0 + g) * HDIM + d0 + 4];
        Qa[kc][3] = qb[(size_t)(q0 + g + 8) * HDIM + d0 + 4];
    }
    int seg0 = g_seg[q0 + g];
    int seg1 = g_seg[q0 + g + 8];

    float m0 = -1e30f, m1 = -1e30f, l0 = 0.f, l1 = 0.f;
    float O[8][4];
#pragma unroll
    for (int nb = 0; nb < 8; nb++)
#pragma unroll
        for (int c = 0; c < 4; c++) O[nb][c] = 0.f;

    int k_lo = g_segstart[n0];
    int k_hi = g_segend[n0 + 63];
    int crow = tid >> 4;      // 0..7
    int cch = tid & 15;       // 0..15

#define STAGE_KV(buf, kt0) do { \
    uint32_t kdst = smem_u32(&Ks[buf][0][0]); \
    uint32_t vdst = smem_u32(&Vs[buf][0][0]); \
    _Pragma("unroll") \
    for (int i_ = 0; i_ < 4; i_++) { \
        int row_ = crow + i_ * 8; \
        int kg_ = (kt0) + row_; \
        int ok_ = (kg_ < k_hi) ? 16 : 0; \
        int kgc_ = (kg_ < k_hi) ? kg_ : (k_hi - 1); \
        uint32_t doff_ = (uint32_t)(row_ * 272 + cch * 16); \
        CP_ASYNC16Z(kdst + doff_, kb + (size_t)kgc_ * HDIM + cch * 4, ok_); \
        CP_ASYNC16Z(vdst + doff_, vb + (size_t)kgc_ * HDIM + cch * 4, ok_); \
    } \
    if (tid < 32) { int kg_ = (kt0) + tid; Sgs[buf][tid] = (kg_ < k_hi) ? g_seg[kg_] : -1; } \
    CP_COMMIT(); \
} while (0)

    STAGE_KV(0, k_lo);
    int nt = (k_hi - k_lo + 31) >> 5;

    for (int it = 0; it < nt; it++) {
        int buf = it & 1;
        if (it + 1 < nt) {
            STAGE_KV(buf ^ 1, k_lo + (it + 1) * 32);
            asm volatile("cp.async.wait_group 1;" ::: "memory");
        } else {
            asm volatile("cp.async.wait_group 0;" ::: "memory");
        }
        __syncthreads();

        // ---- scores: S[16 x 32] = Q @ K^T ----
        float S[4][4];
#pragma unroll
        for (int nb = 0; nb < 4; nb++)
#pragma unroll
            for (int c = 0; c < 4; c++) S[nb][c] = 0.f;
#pragma unroll
        for (int kc = 0; kc < 8; kc++) {
#pragma unroll
            for (int nb = 0; nb < 4; nb++) {
                uint32_t b[2];
                b[0] = Ks[buf][nb * 8 + g][kc * 8 + t];
                b[1] = Ks[buf][nb * 8 + g][kc * 8 + t + 4];
                mma_tf32(S[nb], Qa[kc], b);
            }
        }

        // ---- segment mask + online softmax ----
        float mx0 = -1e30f, mx1 = -1e30f;
#pragma unroll
        for (int nb = 0; nb < 4; nb++) {
            int sa = Sgs[buf][nb * 8 + 2 * t];
            int sb = Sgs[buf][nb * 8 + 2 * t + 1];
            S[nb][0] = (sa == seg0) ? S[nb][0] : -1e30f;
            S[nb][1] = (sb == seg0) ? S[nb][1] : -1e30f;
            S[nb][2] = (sa == seg1) ? S[nb][2] : -1e30f;
            S[nb][3] = (sb == seg1) ? S[nb][3] : -1e30f;
            mx0 = fmaxf(mx0, fmaxf(S[nb][0], S[nb][1]));
            mx1 = fmaxf(mx1, fmaxf(S[nb][2], S[nb][3]));
        }
        mx0 = fmaxf(mx0, __shfl_xor_sync(0xffffffffu, mx0, 1));
        mx0 = fmaxf(mx0, __shfl_xor_sync(0xffffffffu, mx0, 2));
        mx1 = fmaxf(mx1, __shfl_xor_sync(0xffffffffu, mx1, 1));
        mx1 = fmaxf(mx1, __shfl_xor_sync(0xffffffffu, mx1, 2));

        float m0n = fmaxf(m0, mx0);
        float m1n = fmaxf(m1, mx1);
        float corr0 = __expf(m0 - m0n);
        float corr1 = __expf(m1 - m1n);
        l0 *= corr0;
        l1 *= corr1;
#pragma unroll
        for (int nb = 0; nb < 8; nb++) {
            O[nb][0] *= corr0; O[nb][1] *= corr0;
            O[nb][2] *= corr1; O[nb][3] *= corr1;
        }
#pragma unroll
        for (int nb = 0; nb < 4; nb++) {
            float p0 = (S[nb][0] == -1e30f) ? 0.f : __expf(S[nb][0] - m0n);
            float p1 = (S[nb][1] == -1e30f) ? 0.f : __expf(S[nb][1] - m0n);
            float p2 = (S[nb][2] == -1e30f) ? 0.f : __expf(S[nb][2] - m1n);
            float p3 = (S[nb][3] == -1e30f) ? 0.f : __expf(S[nb][3] - m1n);
            l0 += p0 + p1;
            l1 += p2 + p3;
            *(uint2*)&Ps[warp][g][nb * 8 + 2 * t]     = make_uint2(f2tf(p0), f2tf(p1));
            *(uint2*)&Ps[warp][g + 8][nb * 8 + 2 * t] = make_uint2(f2tf(p2), f2tf(p3));
        }
        m0 = m0n;
        m1 = m1n;
        __syncwarp();

        // ---- O += P @ V ----
#pragma unroll
        for (int kc2 = 0; kc2 < 4; kc2++) {
            uint32_t Pa[4];
            Pa[0] = Ps[warp][g][kc2 * 8 + t];
            Pa[1] = Ps[warp][g + 8][kc2 * 8 + t];
            Pa[2] = Ps[warp][g][kc2 * 8 + t + 4];
            Pa[3] = Ps[warp][g + 8][kc2 * 8 + t + 4];
#pragma unroll
            for (int nb = 0; nb < 8; nb++) {
                uint32_t b[2];
                b[0] = Vs[buf][kc2 * 8 + t][nb * 8 + g];
                b[1] = Vs[buf][kc2 * 8 + t + 4][nb * 8 + g];
                mma_tf32(O[nb], Pa, b);
            }
        }
        __syncthreads();
    }
#undef STAGE_KV

    l0 += __shfl_xor_sync(0xffffffffu, l0, 1);
    l0 += __shfl_xor_sync(0xffffffffu, l0, 2);
    l1 += __shfl_xor_sync(0xffffffffu, l1, 1);
    l1 += __shfl_xor_sync(0xffffffffu, l1, 2);
    float inv0 = 1.f / l0;
    float inv1 = 1.f / l1;

    uint32_t* ob = g_atf + h * HDIM;
#pragma unroll
    for (int nb = 0; nb < 8; nb++) {
        int d = nb * 8 + 2 * t;
        *(uint2*)&ob[(size_t)(q0 + g) * EMBED + d] =
            make_uint2(f2tf(O[nb][0] * inv0), f2tf(O[nb][1] * inv0));
        *(uint2*)&ob[(size_t)(q0 + g + 8) * EMBED + d] =
            make_uint2(f2tf(O[nb][2] * inv1), f2tf(O[nb][3] * inv1));
    }
}

// ---------------- residual + layernorm ----------------
__device__ __forceinline__ float block_reduce_sum(float v) {
    __shared__ float sh[8];
    int lane = threadIdx.x & 31, w = threadIdx.x >> 5;
#pragma unroll
    for (int o = 16; o; o >>= 1) v += __shfl_xor_sync(0xffffffffu, v, o);
    if (!lane) sh[w] = v;
    __syncthreads();
    if (w == 0) {
        v = (lane < 8) ? sh[lane] : 0.f;
#pragma unroll
        for (int o = 4; o; o >>= 1) v += __shfl_xor_sync(0xffffffffu, v, o);
        if (!lane) sh[0] = v;
    }
    __syncthreads();
    float r = sh[0];
    __syncthreads();
    return r;
}

__global__ __launch_bounds__(256) void ln_kernel(
    const float* __restrict__ A, const float* __restrict__ R,
    const float* __restrict__ g, const float* __restrict__ b,
    float* __restrict__ out, uint32_t* __restrict__ outtf) {
    int row = blockIdx.x;
    int tid = threadIdx.x;
    const float* a = A + (size_t)row * EMBED;
    const float* r = R + (size_t)row * EMBED;
    float x[4];
    float s = 0.f;
#pragma unroll
    for (int i = 0; i < 4; i++) {
        x[i] = a[tid + i * 256] + r[tid + i * 256];
        s += x[i];
    }
    float mu = block_reduce_sum(s) * (1.0f / EMBED);
    float sq = 0.f;
#pragma unroll
    for (int i = 0; i < 4; i++) {
        float d = x[i] - mu;
        sq += d * d;
    }
    float var = block_reduce_sum(sq) * (1.0f / EMBED);
    float inv = rsqrtf(var + 1e-5f);
#pragma unroll
    for (int i = 0; i < 4; i++) {
        int c = tid + i * 256;
        float v = (x[i] - mu) * inv * g[c] + b[c];
        out[(size_t)row * EMBED + c] = v;
        if (outtf) outtf[(size_t)row * EMBED + c] = f2tf(v);
    }
}

// ---------------- launch ----------------
extern "C" void kernel_launch(void* const* d_in, const int* in_sizes, int n_in,
                              void* d_out, int out_size) {
    const float* coords   = (const float*)d_in[0];
    const float* feats    = (const float*)d_in[1];
    const int*   cu       = (const int*)  d_in[2];
    const float* Wqkv     = (const float*)d_in[3];
    const float* bqkv     = (const float*)d_in[4];
    const float* Wo       = (const float*)d_in[5];
    const float* bo       = (const float*)d_in[6];
    const float* inv_freq = (const float*)d_in[7];
    const float* ln1_g    = (const float*)d_in[8];
    const float* ln1_b    = (const float*)d_in[9];
    const float* W1       = (const float*)d_in[10];
    const float* b1       = (const float*)d_in[11];
    const float* W2       = (const float*)d_in[12];
    const float* b2       = (const float*)d_in[13];
    const float* ln2_g    = (const float*)d_in[14];
    const float* ln2_b    = (const float*)d_in[15];
    float* out = (float*)d_out;

    float *p_qkv, *p_o, *p_h, *p_f2;
    uint32_t *p_wt, *p_ftf, *p_atf, *p_htf, *p_f1tf;
    cudaGetSymbolAddress((void**)&p_qkv,  g_qkv);
    cudaGetSymbolAddress((void**)&p_o,    g_o);
    cudaGetSymbolAddress((void**)&p_h,    g_h);
    cudaGetSymbolAddress((void**)&p_f2,   g_f2);
    cudaGetSymbolAddress((void**)&p_wt,   g_wt);
    cudaGetSymbolAddress((void**)&p_ftf,  g_ftf);
    cudaGetSymbolAddress((void**)&p_atf,  g_atf);
    cudaGetSymbolAddress((void**)&p_htf,  g_htf);
    cudaGetSymbolAddress((void**)&p_f1tf, g_f1tf);

    const size_t off_qkv = 0;
    const size_t off_o   = 3145728;
    const size_t off_1   = 4194304;
    const size_t off_2   = 8388608;

    cudaFuncSetAttribute(gemm_cp<0>, cudaFuncAttributeMaxDynamicSharedMemorySize, GSM_BYTES);
    cudaFuncSetAttribute(gemm_cp<1>, cudaFuncAttributeMaxDynamicSharedMemorySize, GSM_BYTES);

    // 0. operand pre-conversion
    wt_kernel<<<dim3(QKV3 / 32, EMBED / 32), dim3(32, 8)>>>(Wqkv, p_wt + off_qkv, EMBED, QKV3);
    wt_kernel<<<dim3(EMBED / 32, EMBED / 32), dim3(32, 8)>>>(Wo, p_wt + off_o, EMBED, EMBED);
    wt_kernel<<<dim3(FFN / 32, EMBED / 32), dim3(32, 8)>>>(W1, p_wt + off_1, EMBED, FFN);
    wt_kernel<<<dim3(EMBED / 32, FFN / 32), dim3(32, 8)>>>(W2, p_wt + off_2, FFN, EMBED);
    xcvt_kernel<<<(N_TOK * EMBED + 255) / 256, 256>>>(feats, p_ftf, N_TOK * EMBED);

    // 1. segments
    seg_kernel<<<(N_TOK + 255) / 256, 256>>>(cu);

    // 2. qkv = feats @ Wqkv + bqkv
    gemm_cp<0><<<dim3(QKV3 / 128, N_TOK / 128), 256, GSM_BYTES>>>(
        p_ftf, p_wt + off_qkv, bqkv, p_qkv, N_TOK, QKV3, EMBED);

    // 3. rope + head-major tf32 q/k/v
    ropecvt_kernel<<<(N_TOK * NHEAD * 32 + 255) / 256, 256>>>(coords, inv_freq);

    // 4. attention -> g_atf (tf32)
    attn_mma_kernel<<<dim3(N_TOK / 64, NHEAD), 128>>>();

    // 5. o = att @ Wo + bo
    gemm_cp<0><<<dim3(EMBED / 128, N_TOK / 128), 256, GSM_BYTES>>>(
        p_atf, p_wt + off_o, bo, p_o, N_TOK, EMBED, EMBED);

    // 6. h = LN1(feats + o)  (+ tf32 copy)
    ln_kernel<<<N_TOK, 256>>>(feats, p_o, ln1_g, ln1_b, p_h, p_htf);

    // 7. f1 = gelu(h @ W1 + b1) -> tf32 only
    gemm_cp<1><<<dim3(FFN / 128, N_TOK / 128), 256, GSM_BYTES>>>(
        p_htf, p_wt + off_1, b1, p_f1tf, N_TOK, FFN, EMBED);

    // 8. f2 = f1 @ W2 + b2
    gemm_cp<0><<<dim3(EMBED / 128, N_TOK / 128), 256, GSM_BYTES>>>(
        p_f1tf, p_wt + off_2, b2, p_f2, N_TOK, EMBED, FFN);

    // 9. out = LN2(h + f2)
    ln_kernel<<<N_TOK, 256>>>(p_h, p_f2, ln2_g, ln2_b, out, nullptr);
}